// round 12
// baseline (speedup 1.0000x reference)
#include <cuda_runtime.h>
#include <math.h>

#define B_ 8
#define N_ 9216
#define C_ 256
#define O_ 512
#define KS_ 16
#define CHK_ (N_/KS_)      // 576
#define LN_EPS 1e-5f

typedef unsigned int uint;

// ---------------- scratch ----------------------------------------------------
__device__ float  g_qe [B_*N_*C_];   // tf32-rounded unnormalized exp(LN(x2))
__device__ float  g_qs [B_*N_];      // channel sum-exp per row (fp32)
__device__ float  g_n1 [B_*N_*C_];   // tf32-rounded LN(x1)
__device__ float  g_S  [B_*C_];      // N-softmax denom per (b,d)
__device__ float  g_ctxp[(size_t)KS_*B_*C_*C_];
__device__ float  g_ctx[B_*C_*C_];
__device__ float  g_WA [B_*O_*C_];   // tf32-rounded

// ---------------- fast exp (FMA only) ----------------------------------------
__device__ __forceinline__ float fexp(float x) {
    float t = fmaf(x, 1.4426950408889634f, 12582912.0f);
    float n = t - 12582912.0f;
    int ni = __float_as_int(t) - 0x4B400000;
    float r = fmaf(n, -0.693359375f, x);
    r = fmaf(n, 2.12194440e-4f, r);
    float z = r * r;
    float p = 1.9875691500E-4f;
    p = fmaf(p, r, 1.3981999507E-3f);
    p = fmaf(p, r, 8.3334519073E-3f);
    p = fmaf(p, r, 4.1665795894E-2f);
    p = fmaf(p, r, 1.6666665459E-1f);
    p = fmaf(p, r, 5.0000001201E-1f);
    float res = fmaf(z, p, r) + 1.0f;
    res = __int_as_float(__float_as_int(res) + (ni << 23));
    return (x > -80.0f) ? res : 0.0f;
}

// ---------------- tf32 helpers -----------------------------------------------
__device__ __forceinline__ uint tf32c(float f) {
    uint r;
    asm("cvt.rna.tf32.f32 %0, %1;" : "=r"(r) : "f"(f));
    return r;
}
__device__ __forceinline__ float tf32f(float f) { return __uint_as_float(tf32c(f)); }
__device__ __forceinline__ void mma8(float4& d, const uint* a, const uint* b) {
    asm volatile("mma.sync.aligned.m16n8k8.row.col.f32.tf32.tf32.f32 "
        "{%0,%1,%2,%3}, {%4,%5,%6,%7}, {%8,%9}, {%0,%1,%2,%3};"
        : "+f"(d.x), "+f"(d.y), "+f"(d.z), "+f"(d.w)
        : "r"(a[0]), "r"(a[1]), "r"(a[2]), "r"(a[3]), "r"(b[0]), "r"(b[1]));
}
__device__ __forceinline__ uint smem_u32(const void* p) {
    uint a;
    asm("{ .reg .u64 t; cvta.to.shared.u64 t, %1; cvt.u32.u64 %0, t; }"
        : "=r"(a) : "l"(p));
    return a;
}
__device__ __forceinline__ void cp16(uint dst, const void* src) {
    asm volatile("cp.async.cg.shared.global [%0], [%1], 16;"
                 :: "r"(dst), "l"(src) : "memory");
}
#define CP_COMMIT() asm volatile("cp.async.commit_group;" ::: "memory")
#define CP_WAITN(n) asm volatile("cp.async.wait_group %0;" :: "n"(n) : "memory")

// ---------------- block reductions (256 threads) -----------------------------
__device__ __forceinline__ float blkSum(float v, float* sh) {
    #pragma unroll
    for (int o = 16; o > 0; o >>= 1) v += __shfl_down_sync(0xffffffffu, v, o);
    int w = threadIdx.x >> 5;
    if ((threadIdx.x & 31) == 0) sh[w] = v;
    __syncthreads();
    if (threadIdx.x < 32) {
        float x = (threadIdx.x < 8) ? sh[threadIdx.x] : 0.f;
        #pragma unroll
        for (int o = 4; o > 0; o >>= 1) x += __shfl_down_sync(0xffffffffu, x, o);
        if (threadIdx.x == 0) sh[0] = x;
    }
    __syncthreads();
    float r = sh[0];
    __syncthreads();
    return r;
}
__device__ __forceinline__ float blkMax(float v, float* sh) {
    #pragma unroll
    for (int o = 16; o > 0; o >>= 1) v = fmaxf(v, __shfl_xor_sync(0xffffffffu, v, o));
    int w = threadIdx.x >> 5;
    if ((threadIdx.x & 31) == 0) sh[w] = v;
    __syncthreads();
    if (threadIdx.x < 32) {
        float x = (threadIdx.x < 8) ? sh[threadIdx.x] : -INFINITY;
        #pragma unroll
        for (int o = 4; o > 0; o >>= 1) x = fmaxf(x, __shfl_xor_sync(0xffffffffu, x, o));
        if (threadIdx.x == 0) sh[0] = x;
    }
    __syncthreads();
    float r = sh[0];
    __syncthreads();
    return r;
}

// ---------------- merged producers (+ fused column-sum of qe) ------------------
__global__ void prod_kernel(const float* __restrict__ x1,
                            const float* __restrict__ x2,
                            const float* __restrict__ w,
                            const float* __restrict__ b,
                            float* __restrict__ n1,
                            float* __restrict__ qe,
                            float* __restrict__ qs,
                            float* __restrict__ Sg) {
    __shared__ float se_[8][C_];
    int warp = threadIdx.x >> 5, lane = threadIdx.x & 31;
    size_t row = (size_t)blockIdx.x * 8 + warp;
    const float* x = (blockIdx.y == 0) ? x1 : x2;
    const float4* xr = (const float4*)(x + row * C_);
    float4 v0 = xr[lane], v1 = xr[lane + 32];
    float s  = v0.x + v0.y + v0.z + v0.w + v1.x + v1.y + v1.z + v1.w;
    float s2 = v0.x*v0.x + v0.y*v0.y + v0.z*v0.z + v0.w*v0.w
             + v1.x*v1.x + v1.y*v1.y + v1.z*v1.z + v1.w*v1.w;
    #pragma unroll
    for (int o = 16; o > 0; o >>= 1) {
        s  += __shfl_xor_sync(0xffffffffu, s, o);
        s2 += __shfl_xor_sync(0xffffffffu, s2, o);
    }
    float mu = s * (1.f / C_);
    float rsd = rsqrtf(s2 * (1.f / C_) - mu * mu + LN_EPS);
    float4 w0 = ((const float4*)w)[lane], w1 = ((const float4*)w)[lane + 32];
    float4 b0 = ((const float4*)b)[lane], b1 = ((const float4*)b)[lane + 32];
    float4 l0, l1;
    l0.x = (v0.x - mu) * rsd * w0.x + b0.x;
    l0.y = (v0.y - mu) * rsd * w0.y + b0.y;
    l0.z = (v0.z - mu) * rsd * w0.z + b0.z;
    l0.w = (v0.w - mu) * rsd * w0.w + b0.w;
    l1.x = (v1.x - mu) * rsd * w1.x + b1.x;
    l1.y = (v1.y - mu) * rsd * w1.y + b1.y;
    l1.z = (v1.z - mu) * rsd * w1.z + b1.z;
    l1.w = (v1.w - mu) * rsd * w1.w + b1.w;
    if (blockIdx.y == 0) {
        float4 o0, o1;
        o0.x = tf32f(l0.x); o0.y = tf32f(l0.y); o0.z = tf32f(l0.z); o0.w = tf32f(l0.w);
        o1.x = tf32f(l1.x); o1.y = tf32f(l1.y); o1.z = tf32f(l1.z); o1.w = tf32f(l1.w);
        float4* outr = (float4*)(n1 + row * C_);
        outr[lane] = o0; outr[lane + 32] = o1;
    } else {
        float4 e0, e1;
        e0.x = fexp(l0.x); e0.y = fexp(l0.y); e0.z = fexp(l0.z); e0.w = fexp(l0.w);
        e1.x = fexp(l1.x); e1.y = fexp(l1.y); e1.z = fexp(l1.z); e1.w = fexp(l1.w);
        float se = e0.x + e0.y + e0.z + e0.w + e1.x + e1.y + e1.z + e1.w;
        #pragma unroll
        for (int o = 16; o > 0; o >>= 1) se += __shfl_xor_sync(0xffffffffu, se, o);
        float4 t0, t1;
        t0.x = tf32f(e0.x); t0.y = tf32f(e0.y); t0.z = tf32f(e0.z); t0.w = tf32f(e0.w);
        t1.x = tf32f(e1.x); t1.y = tf32f(e1.y); t1.z = tf32f(e1.z); t1.w = tf32f(e1.w);
        float4* qer = (float4*)(qe + row * C_);
        qer[lane] = t0; qer[lane + 32] = t1;
        if (lane == 0) qs[row] = se;
        // stage rounded values for column sums (S accumulation)
        *(float4*)&se_[warp][lane * 4] = t0;
        *(float4*)&se_[warp][128 + lane * 4] = t1;
        __syncthreads();
        int t = threadIdx.x;   // 0..255 = channel
        float cs = 0.f;
        #pragma unroll
        for (int r = 0; r < 8; r++) cs += se_[r][t];
        int bb = (int)(row / N_);
        atomicAdd(&Sg[bb * C_ + t], cs);
    }
}

// ---------------- zero S ------------------------------------------------------
__global__ void zero_kernel(float* __restrict__ p, int n) {
    int i = blockIdx.x * 256 + threadIdx.x;
    if (i < n) p[i] = 0.f;
}

// ---------------- context GEMM: pure tf32 mma, cp.async 4-stage ---------------
#define CSTAGEW (2 * 16 * 136)            // words per stage (sa+sb) = 4352
#define CSMEM   (4 * CSTAGEW * 4)         // 69632 B
__global__ __launch_bounds__(256) void ctx_gemm(
        const float* __restrict__ qe, const float* __restrict__ n1,
        float* __restrict__ ctxp) {
    extern __shared__ __align__(16) uint cpool[];
    int bz = blockIdx.z;
    int b = bz / KS_, sk = bz % KS_;
    int m0 = blockIdx.y * 128, n0 = blockIdx.x * 128;
    const float* A  = qe + (size_t)b * N_ * C_;
    const float* Bx = n1 + (size_t)b * N_ * C_;

    int t = threadIdx.x;
    int warp = t >> 5, lane = t & 31, g = lane >> 2, tg = lane & 3;
    int wm = (warp >> 2) * 64, wn = (warp & 3) * 32;
    int kk0 = t >> 5, kk1 = 8 + kk0, m4 = (t & 31) * 4;
    int kbase = sk * CHK_;
    uint abase = smem_u32(cpool);

    float4 acc[4][4];
    #pragma unroll
    for (int i = 0; i < 4; i++)
        #pragma unroll
        for (int j = 0; j < 4; j++) acc[i][j] = make_float4(0.f, 0.f, 0.f, 0.f);

    auto ISSUE = [&](int kt) {
        int buf = kt & 3;
        int r0 = kbase + kt * 16 + kk0, r1 = kbase + kt * 16 + kk1;
        uint base = abase + (uint)buf * (CSTAGEW * 4);
        cp16(base + (uint)(kk0 * 136 + m4) * 4, &A[(size_t)r0 * C_ + m0 + m4]);
        cp16(base + (uint)(kk1 * 136 + m4) * 4, &A[(size_t)r1 * C_ + m0 + m4]);
        cp16(base + (uint)(16 * 136 + kk0 * 136 + m4) * 4, &Bx[(size_t)r0 * C_ + n0 + m4]);
        cp16(base + (uint)(16 * 136 + kk1 * 136 + m4) * 4, &Bx[(size_t)r1 * C_ + n0 + m4]);
        CP_COMMIT();
    };

    const int NT = CHK_ / 16;   // 36
    ISSUE(0); ISSUE(1); ISSUE(2);
    for (int kt = 0; kt < NT; kt++) {
        // allow exactly the groups newer than stage kt to remain in flight
        int rem = NT - 1 - kt;
        if (rem >= 2)      { CP_WAITN(2); }
        else if (rem == 1) { CP_WAITN(1); }
        else               { CP_WAITN(0); }
        __syncthreads();
        if (kt + 3 < NT) ISSUE(kt + 3);
        const uint* sa = cpool + (kt & 3) * CSTAGEW;
        const uint* sb = sa + 16 * 136;
        #pragma unroll
        for (int ks = 0; ks < 16; ks += 8) {
            uint afr[4][4], bfr[4][2];
            #pragma unroll
            for (int mt = 0; mt < 4; mt++) {
                int m = wm + mt * 16 + g;
                afr[mt][0] = sa[(ks + tg) * 136 + m];
                afr[mt][1] = sa[(ks + tg) * 136 + m + 8];
                afr[mt][2] = sa[(ks + tg + 4) * 136 + m];
                afr[mt][3] = sa[(ks + tg + 4) * 136 + m + 8];
            }
            #pragma unroll
            for (int nt = 0; nt < 4; nt++) {
                int n = wn + nt * 8 + g;
                bfr[nt][0] = sb[(ks + tg) * 136 + n];
                bfr[nt][1] = sb[(ks + tg + 4) * 136 + n];
            }
            #pragma unroll
            for (int mt = 0; mt < 4; mt++)
                #pragma unroll
                for (int nt = 0; nt < 4; nt++)
                    mma8(acc[mt][nt], afr[mt], bfr[nt]);
        }
    }

    float* dst = ctxp + ((size_t)sk * B_ + b) * C_ * C_;
    #pragma unroll
    for (int mt = 0; mt < 4; mt++) {
        int row = m0 + wm + mt * 16 + g;
        #pragma unroll
        for (int nt = 0; nt < 4; nt++) {
            int col = n0 + wn + nt * 8 + tg * 2;
            *(float2*)&dst[(size_t)row * C_ + col] = make_float2(acc[mt][nt].x, acc[mt][nt].y);
            *(float2*)&dst[(size_t)(row + 8) * C_ + col] = make_float2(acc[mt][nt].z, acc[mt][nt].w);
        }
    }
}

// ---------------- combined 4-way top-k masked softmax ------------------------
__global__ void topk_kernel(const float* __restrict__ ctxp, float* __restrict__ ctx,
                            const float* __restrict__ aw, const float* __restrict__ Sg) {
    __shared__ float sc[C_];
    __shared__ float sh[8];
    int row = blockIdx.x;
    int b = row >> 8, d = row & 255;
    int t = threadIdx.x;
    float v = 0.f;
    #pragma unroll
    for (int sk = 0; sk < KS_; sk++)
        v += ctxp[(((size_t)sk * B_ + b) * C_ + d) * C_ + t];
    v /= Sg[row];
    sc[t] = v;
    __syncthreads();
    int rank = 0;
    #pragma unroll 8
    for (int f = 0; f < C_; f++) {
        float vf = sc[f];
        rank += (vf > v) || (vf == v && f < t);
    }
    float m = blkMax(v, sh);
    float e = fexp(v - m);
    float z1 = blkSum(rank < 128 ? e : 0.f, sh);
    float z2 = blkSum(rank < 170 ? e : 0.f, sh);
    float z3 = blkSum(rank < 192 ? e : 0.f, sh);
    float z4 = blkSum(rank < 204 ? e : 0.f, sh);
    float coeff = 0.f;
    if (rank < 128) coeff += aw[0] / z1;
    if (rank < 170) coeff += aw[1] / z2;
    if (rank < 192) coeff += aw[2] / z3;
    if (rank < 204) coeff += aw[3] / z4;
    ctx[(size_t)row * C_ + t] = e * coeff;
}

// ---------------- small GEMM (F1): WA = tf32(reproj_w @ A) --------------------
__global__ void gemm64(const float* __restrict__ A, const float* __restrict__ B,
                       float* __restrict__ C,
                       int K, size_t sA, size_t sB, size_t sC,
                       int lda, int ldb, int ldc) {
    int bz = blockIdx.z;
    const float* Ab = A + (size_t)bz * sA;
    const float* Bb = B + (size_t)bz * sB;
    float* Cb = C + (size_t)bz * sC;
    int m0 = blockIdx.y * 64, n0 = blockIdx.x * 64;
    __shared__ float sa[16][65];
    __shared__ float sb[16][64];
    int t = threadIdx.x;
    int tx = t % 16, ty = t / 16;
    int r_ld = t / 16, kk_lda = t % 16;
    int c_ld = t % 64, kk_ldb = t / 64;
    float acc[4][4] = {};
    for (int k0 = 0; k0 < K; k0 += 16) {
        __syncthreads();
        #pragma unroll
        for (int it = 0; it < 4; it++) {
            sa[kk_lda][r_ld + 16 * it] = Ab[(size_t)(m0 + r_ld + 16 * it) * lda + k0 + kk_lda];
            sb[kk_ldb + 4 * it][c_ld] = Bb[(size_t)(k0 + kk_ldb + 4 * it) * ldb + n0 + c_ld];
        }
        __syncthreads();
        #pragma unroll
        for (int kk = 0; kk < 16; kk++) {
            float av[4], bv[4];
            #pragma unroll
            for (int i = 0; i < 4; i++) av[i] = sa[kk][ty + 16 * i];
            #pragma unroll
            for (int j = 0; j < 4; j++) bv[j] = sb[kk][tx + 16 * j];
            #pragma unroll
            for (int i = 0; i < 4; i++)
                #pragma unroll
                for (int j = 0; j < 4; j++) acc[i][j] = fmaf(av[i], bv[j], acc[i][j]);
        }
    }
    #pragma unroll
    for (int i = 0; i < 4; i++)
        #pragma unroll
        for (int j = 0; j < 4; j++)
            Cb[(size_t)(m0 + ty + 16 * i) * ldc + n0 + tx + 16 * j] = tf32f(acc[i][j]);
}

// ---------------- final: rp = (qe @ WA^T)/qs + bias -> LN -> NCHW -------------
#define FSTAGEW ((64 + 512) * 8)          // words per k8 stage = 4608
#define FSMEM   (6 * FSTAGEW * 4)         // 110592 B (6 stages)
__global__ __launch_bounds__(512) void final_kernel(
        const float* __restrict__ qe, const float* __restrict__ qsg,
        const float* __restrict__ WA,
        const float* __restrict__ rbias, const float* __restrict__ w2g,
        const float* __restrict__ b2g, float* __restrict__ out) {
    extern __shared__ __align__(16) uint pool[];

    int bb = blockIdx.y;
    int n0 = blockIdx.x * 64;
    const float* qb  = qe + (size_t)bb * N_ * C_ + (size_t)n0 * C_;
    const float* WAb = WA + (size_t)bb * O_ * C_;

    int t = threadIdx.x, warp = t >> 5, lane = t & 31, g = lane >> 2, tg = lane & 3;
    int o0 = warp * 32;
    uint abase = smem_u32(pool);

    float4 acc[4][4];
    #pragma unroll
    for (int i = 0; i < 4; i++)
        #pragma unroll
        for (int j = 0; j < 4; j++) acc[i][j] = make_float4(0.f, 0.f, 0.f, 0.f);

    auto ISSUE = [&](int kt) {
        int buf = kt % 6;
        int k0 = kt * 8;
        uint base = abase + (uint)buf * (FSTAGEW * 4);
        #pragma unroll
        for (int i = 0; i < 3; i++) {
            int c = t + 512 * i;
            if (i < 2 || t < 128) {
                int row = c >> 1, half = c & 1;
                const float* src = (row < 64)
                    ? &qb[(size_t)row * C_ + k0 + half * 4]
                    : &WAb[(size_t)(row - 64) * C_ + k0 + half * 4];
                cp16(base + (uint)(row * 8 + half * 4) * 4, src);
            }
        }
        CP_COMMIT();
    };

    const int NT = C_ / 8;   // 32
    ISSUE(0); ISSUE(1); ISSUE(2); ISSUE(3); ISSUE(4);
    for (int kt = 0; kt < NT; kt++) {
        int rem = NT - 1 - kt;
        if (rem >= 4)      { CP_WAITN(4); }
        else if (rem == 3) { CP_WAITN(3); }
        else if (rem == 2) { CP_WAITN(2); }
        else if (rem == 1) { CP_WAITN(1); }
        else               { CP_WAITN(0); }
        __syncthreads();
        if (kt + 5 < NT) ISSUE(kt + 5);
        const uint* sq  = pool + (kt % 6) * FSTAGEW;
        const uint* swa = sq + 64 * 8;
        uint afr[4][4], bfr[4][2];
        #pragma unroll
        for (int mt = 0; mt < 4; mt++) {
            int r1 = mt * 16 + g;
            afr[mt][0] = sq[r1 * 8 + tg];
            afr[mt][1] = sq[(r1 + 8) * 8 + tg];
            afr[mt][2] = sq[r1 * 8 + tg + 4];
            afr[mt][3] = sq[(r1 + 8) * 8 + tg + 4];
        }
        #pragma unroll
        for (int nt = 0; nt < 4; nt++) {
            int o = o0 + nt * 8 + g;
            bfr[nt][0] = swa[o * 8 + tg];
            bfr[nt][1] = swa[o * 8 + tg + 4];
        }
        #pragma unroll
        for (int mt = 0; mt < 4; mt++)
            #pragma unroll
            for (int nt = 0; nt < 4; nt++)
                mma8(acc[mt][nt], afr[mt], bfr[nt]);
    }
    __syncthreads();

    // ---- epilogue (pool reused) ----
    float* redS = (float*)pool;            // [16][64]
    float* redQ = (float*)(pool + 1024);   // [16][64]
    float* muS  = (float*)(pool + 2048);   // [64]
    float* rsS  = (float*)(pool + 2112);   // [64]
    float* sout = (float*)(pool + 2176);   // [128][68]

    const float* qsb = qsg + (size_t)bb * N_ + n0;
    float i1[4], i2[4];
    #pragma unroll
    for (int mt = 0; mt < 4; mt++) {
        i1[mt] = 1.f / qsb[mt * 16 + g];
        i2[mt] = 1.f / qsb[mt * 16 + g + 8];
    }
    #pragma unroll
    for (int nt = 0; nt < 4; nt++) {
        int o = o0 + nt * 8 + tg * 2;
        float2 rb = *(const float2*)&rbias[o];
        #pragma unroll
        for (int mt = 0; mt < 4; mt++) {
            acc[mt][nt].x = acc[mt][nt].x * i1[mt] + rb.x;
            acc[mt][nt].y = acc[mt][nt].y * i1[mt] + rb.y;
            acc[mt][nt].z = acc[mt][nt].z * i2[mt] + rb.x;
            acc[mt][nt].w = acc[mt][nt].w * i2[mt] + rb.y;
        }
    }

    #pragma unroll
    for (int mt = 0; mt < 4; mt++) {
        float sA = 0.f, qA = 0.f, sB = 0.f, qB = 0.f;
        #pragma unroll
        for (int nt = 0; nt < 4; nt++) {
            float4 a = acc[mt][nt];
            sA += a.x + a.y; qA += a.x * a.x + a.y * a.y;
            sB += a.z + a.w; qB += a.z * a.z + a.w * a.w;
        }
        #pragma unroll
        for (int o = 1; o <= 2; o <<= 1) {
            sA += __shfl_xor_sync(0xffffffffu, sA, o);
            qA += __shfl_xor_sync(0xffffffffu, qA, o);
            sB += __shfl_xor_sync(0xffffffffu, sB, o);
            qB += __shfl_xor_sync(0xffffffffu, qB, o);
        }
        if (tg == 0) {
            redS[warp * 64 + mt * 16 + g] = sA;
            redQ[warp * 64 + mt * 16 + g] = qA;
            redS[warp * 64 + mt * 16 + g + 8] = sB;
            redQ[warp * 64 + mt * 16 + g + 8] = qB;
        }
    }
    __syncthreads();
    if (t < 64) {
        float s = 0.f, qq = 0.f;
        #pragma unroll
        for (int w = 0; w < 16; w++) { s += redS[w * 64 + t]; qq += redQ[w * 64 + t]; }
        float mu = s * (1.f / O_);
        float var = qq * (1.f / O_) - mu * mu;
        muS[t] = mu;
        rsS[t] = rsqrtf(var + LN_EPS);
    }
    __syncthreads();
    float mu1[4], rs1[4], mu2[4], rs2[4];
    #pragma unroll
    for (int mt = 0; mt < 4; mt++) {
        mu1[mt] = muS[mt * 16 + g];     rs1[mt] = rsS[mt * 16 + g];
        mu2[mt] = muS[mt * 16 + g + 8]; rs2[mt] = rsS[mt * 16 + g + 8];
    }
    __syncthreads();

    #pragma unroll
    for (int p = 0; p < 4; p++) {
        if ((warp >> 2) == p) {
            int obase = (warp & 3) * 32;
            #pragma unroll
            for (int nt = 0; nt < 4; nt++) {
                int ol = obase + nt * 8 + tg * 2;
                int o = p * 128 + ol;
                float2 wv = *(const float2*)&w2g[o];
                float2 bv = *(const float2*)&b2g[o];
                #pragma unroll
                for (int mt = 0; mt < 4; mt++) {
                    int r1 = mt * 16 + g, r2 = r1 + 8;
                    float4 a = acc[mt][nt];
                    sout[ol * 68 + r1]       = (a.x - mu1[mt]) * rs1[mt] * wv.x + bv.x;
                    sout[(ol + 1) * 68 + r1] = (a.y - mu1[mt]) * rs1[mt] * wv.y + bv.y;
                    sout[ol * 68 + r2]       = (a.z - mu2[mt]) * rs2[mt] * wv.x + bv.x;
                    sout[(ol + 1) * 68 + r2] = (a.w - mu2[mt]) * rs2[mt] * wv.y + bv.y;
                }
            }
        }
        __syncthreads();
        #pragma unroll
        for (int i = 0; i < 4; i++) {
            int idx = t + 512 * i;
            int ol = idx >> 4, nn = (idx & 15) * 4;
            float4 v = *(float4*)&sout[ol * 68 + nn];
            *(float4*)&out[((size_t)bb * O_ + p * 128 + ol) * N_ + n0 + nn] = v;
        }
        __syncthreads();
    }
}

// ---------------- launch -----------------------------------------------------
extern "C" void kernel_launch(void* const* d_in, const int* in_sizes, int n_in,
                              void* d_out, int out_size) {
    const float* x1       = (const float*)d_in[0];
    const float* x2       = (const float*)d_in[1];
    const float* norm1_w  = (const float*)d_in[2];
    const float* norm1_b  = (const float*)d_in[3];
    const float* reproj_w = (const float*)d_in[4];
    const float* reproj_b = (const float*)d_in[5];
    const float* norm2_w  = (const float*)d_in[6];
    const float* norm2_b  = (const float*)d_in[7];
    const float* attn_w   = (const float*)d_in[8];
    float* out = (float*)d_out;

    float *qe, *qs, *n1, *S, *ctxp, *ctx, *WA;
    cudaGetSymbolAddress((void**)&qe,   g_qe);
    cudaGetSymbolAddress((void**)&qs,   g_qs);
    cudaGetSymbolAddress((void**)&n1,   g_n1);
    cudaGetSymbolAddress((void**)&S,    g_S);
    cudaGetSymbolAddress((void**)&ctxp, g_ctxp);
    cudaGetSymbolAddress((void**)&ctx,  g_ctx);
    cudaGetSymbolAddress((void**)&WA,   g_WA);

    cudaFuncSetAttribute(ctx_gemm,
                         cudaFuncAttributeMaxDynamicSharedMemorySize, CSMEM);
    cudaFuncSetAttribute(final_kernel,
                         cudaFuncAttributeMaxDynamicSharedMemorySize, FSMEM);

    zero_kernel<<<(B_ * C_ + 255) / 256, 256>>>(S, B_ * C_);
    prod_kernel<<<dim3(B_ * N_ / 8, 2), 256>>>(x1, x2, norm1_w, norm1_b,
                                               n1, qe, qs, S);

    ctx_gemm<<<dim3(2, 2, B_ * KS_), 256, CSMEM>>>(qe, n1, ctxp);

    topk_kernel<<<B_ * C_, 256>>>(ctxp, ctx, attn_w, S);

    gemm64<<<dim3(C_ / 64, O_ / 64, B_), 256>>>(
        reproj_w, ctx, WA, C_,
        (size_t)0, (size_t)C_ * C_, (size_t)O_ * C_,
        C_, C_, C_);

    final_kernel<<<dim3(N_ / 64, B_), 512, FSMEM>>>(
        qe, qs, WA, reproj_b, norm2_w, norm2_b, out);
}

// round 13
// speedup vs baseline: 1.0453x; 1.0453x over previous
#include <cuda_runtime.h>
#include <math.h>

#define B_ 8
#define N_ 9216
#define C_ 256
#define O_ 512
#define KS_ 8
#define CHK_ (N_/KS_)      // 1152
#define NCH_ 72
#define CR_ 128
#define LN_EPS 1e-5f

typedef unsigned int uint;
typedef unsigned long long ull;

// ---------------- scratch ----------------------------------------------------
__device__ float  g_qe [B_*N_*C_];   // tf32-rounded unnormalized exp(LN(x2))
__device__ float  g_qs [B_*N_];      // channel sum-exp per row (fp32)
__device__ float  g_n1 [B_*N_*C_];   // tf32-rounded LN(x1)
__device__ float  g_S  [B_*C_];      // N-softmax denom per (b,d)
__device__ float  g_ctxp[(size_t)KS_*B_*C_*C_];
__device__ float  g_ctx[B_*C_*C_];
__device__ float  g_WA [B_*O_*C_];   // tf32-rounded

// ---------------- fast exp (FMA only) ----------------------------------------
__device__ __forceinline__ float fexp(float x) {
    float t = fmaf(x, 1.4426950408889634f, 12582912.0f);
    float n = t - 12582912.0f;
    int ni = __float_as_int(t) - 0x4B400000;
    float r = fmaf(n, -0.693359375f, x);
    r = fmaf(n, 2.12194440e-4f, r);
    float z = r * r;
    float p = 1.9875691500E-4f;
    p = fmaf(p, r, 1.3981999507E-3f);
    p = fmaf(p, r, 8.3334519073E-3f);
    p = fmaf(p, r, 4.1665795894E-2f);
    p = fmaf(p, r, 1.6666665459E-1f);
    p = fmaf(p, r, 5.0000001201E-1f);
    float res = fmaf(z, p, r) + 1.0f;
    res = __int_as_float(__float_as_int(res) + (ni << 23));
    return (x > -80.0f) ? res : 0.0f;
}

// ---------------- tf32 helpers -----------------------------------------------
__device__ __forceinline__ uint tf32c(float f) {
    uint r;
    asm("cvt.rna.tf32.f32 %0, %1;" : "=r"(r) : "f"(f));
    return r;
}
__device__ __forceinline__ float tf32f(float f) { return __uint_as_float(tf32c(f)); }
__device__ __forceinline__ void mma8(float4& d, const uint* a, const uint* b) {
    asm volatile("mma.sync.aligned.m16n8k8.row.col.f32.tf32.tf32.f32 "
        "{%0,%1,%2,%3}, {%4,%5,%6,%7}, {%8,%9}, {%0,%1,%2,%3};"
        : "+f"(d.x), "+f"(d.y), "+f"(d.z), "+f"(d.w)
        : "r"(a[0]), "r"(a[1]), "r"(a[2]), "r"(a[3]), "r"(b[0]), "r"(b[1]));
}
__device__ __forceinline__ uint smem_u32(const void* p) {
    uint a;
    asm("{ .reg .u64 t; cvta.to.shared.u64 t, %1; cvt.u32.u64 %0, t; }"
        : "=r"(a) : "l"(p));
    return a;
}
__device__ __forceinline__ void cp16(uint dst, const void* src) {
    asm volatile("cp.async.cg.shared.global [%0], [%1], 16;"
                 :: "r"(dst), "l"(src) : "memory");
}
#define CP_COMMIT() asm volatile("cp.async.commit_group;" ::: "memory")
#define CP_WAIT1()  asm volatile("cp.async.wait_group 1;" ::: "memory")
#define CP_WAIT0()  asm volatile("cp.async.wait_group 0;" ::: "memory")

// ---------------- merged producers: y=0 -> n1 from x1; y=1 -> qe/qs from x2 ---
__global__ void prod_kernel(const float* __restrict__ x1,
                            const float* __restrict__ x2,
                            const float* __restrict__ w,
                            const float* __restrict__ b,
                            float* __restrict__ n1,
                            float* __restrict__ qe,
                            float* __restrict__ qs) {
    int warp = threadIdx.x >> 5, lane = threadIdx.x & 31;
    size_t row = (size_t)blockIdx.x * 8 + warp;
    const float* x = (blockIdx.y == 0) ? x1 : x2;
    const float4* xr = (const float4*)(x + row * C_);
    float4 v0 = xr[lane], v1 = xr[lane + 32];
    float s  = v0.x + v0.y + v0.z + v0.w + v1.x + v1.y + v1.z + v1.w;
    float s2 = v0.x*v0.x + v0.y*v0.y + v0.z*v0.z + v0.w*v0.w
             + v1.x*v1.x + v1.y*v1.y + v1.z*v1.z + v1.w*v1.w;
    #pragma unroll
    for (int o = 16; o > 0; o >>= 1) {
        s  += __shfl_xor_sync(0xffffffffu, s, o);
        s2 += __shfl_xor_sync(0xffffffffu, s2, o);
    }
    float mu = s * (1.f / C_);
    float rsd = rsqrtf(s2 * (1.f / C_) - mu * mu + LN_EPS);
    float4 w0 = ((const float4*)w)[lane], w1 = ((const float4*)w)[lane + 32];
    float4 b0 = ((const float4*)b)[lane], b1 = ((const float4*)b)[lane + 32];
    float4 l0, l1;
    l0.x = (v0.x - mu) * rsd * w0.x + b0.x;
    l0.y = (v0.y - mu) * rsd * w0.y + b0.y;
    l0.z = (v0.z - mu) * rsd * w0.z + b0.z;
    l0.w = (v0.w - mu) * rsd * w0.w + b0.w;
    l1.x = (v1.x - mu) * rsd * w1.x + b1.x;
    l1.y = (v1.y - mu) * rsd * w1.y + b1.y;
    l1.z = (v1.z - mu) * rsd * w1.z + b1.z;
    l1.w = (v1.w - mu) * rsd * w1.w + b1.w;
    if (blockIdx.y == 0) {
        float4 o0, o1;
        o0.x = tf32f(l0.x); o0.y = tf32f(l0.y); o0.z = tf32f(l0.z); o0.w = tf32f(l0.w);
        o1.x = tf32f(l1.x); o1.y = tf32f(l1.y); o1.z = tf32f(l1.z); o1.w = tf32f(l1.w);
        float4* outr = (float4*)(n1 + row * C_);
        outr[lane] = o0; outr[lane + 32] = o1;
    } else {
        float4 e0, e1;
        e0.x = fexp(l0.x); e0.y = fexp(l0.y); e0.z = fexp(l0.z); e0.w = fexp(l0.w);
        e1.x = fexp(l1.x); e1.y = fexp(l1.y); e1.z = fexp(l1.z); e1.w = fexp(l1.w);
        float se = e0.x + e0.y + e0.z + e0.w + e1.x + e1.y + e1.z + e1.w;
        #pragma unroll
        for (int o = 16; o > 0; o >>= 1) se += __shfl_xor_sync(0xffffffffu, se, o);
        float4 t0, t1;
        t0.x = tf32f(e0.x); t0.y = tf32f(e0.y); t0.z = tf32f(e0.z); t0.w = tf32f(e0.w);
        t1.x = tf32f(e1.x); t1.y = tf32f(e1.y); t1.z = tf32f(e1.z); t1.w = tf32f(e1.w);
        float4* qer = (float4*)(qe + row * C_);
        qer[lane] = t0; qer[lane + 32] = t1;
        if (lane == 0) qs[row] = se;
    }
}

// ---------------- zero + column sum (S) ---------------------------------------
__global__ void zero_kernel(float* __restrict__ p, int n) {
    int i = blockIdx.x * 256 + threadIdx.x;
    if (i < n) p[i] = 0.f;
}
__global__ void colsum_kernel(const float* __restrict__ qe, float* __restrict__ S) {
    int b = blockIdx.y, ch = blockIdx.x, t = threadIdx.x;
    const float* base = qe + ((size_t)b * N_ + (size_t)ch * CR_) * C_ + t;
    float s = 0.f;
    #pragma unroll 8
    for (int r = 0; r < CR_; r++) s += base[(size_t)r * C_];
    atomicAdd(&S[b * C_ + t], s);
}

// ---------------- context GEMM: pure tf32 mma, cp.async 3-stage ---------------
#define CSTAGEW (2 * 16 * 136)            // words per stage (sa+sb)
#define CSMEM   (3 * CSTAGEW * 4)         // 52224 B
__global__ __launch_bounds__(256) void ctx_gemm(
        const float* __restrict__ qe, const float* __restrict__ n1,
        float* __restrict__ ctxp) {
    extern __shared__ __align__(16) uint cpool[];
    int bz = blockIdx.z;
    int b = bz / KS_, sk = bz % KS_;
    int m0 = blockIdx.y * 128, n0 = blockIdx.x * 128;
    const float* A  = qe + (size_t)b * N_ * C_;
    const float* Bx = n1 + (size_t)b * N_ * C_;

    int t = threadIdx.x;
    int warp = t >> 5, lane = t & 31, g = lane >> 2, tg = lane & 3;
    int wm = (warp >> 2) * 64, wn = (warp & 3) * 32;
    int kk0 = t >> 5, kk1 = 8 + kk0, m4 = (t & 31) * 4;
    int kbase = sk * CHK_;
    uint abase = smem_u32(cpool);

    float4 acc[4][4];
    #pragma unroll
    for (int i = 0; i < 4; i++)
        #pragma unroll
        for (int j = 0; j < 4; j++) acc[i][j] = make_float4(0.f, 0.f, 0.f, 0.f);

    auto ISSUE = [&](int kt, int buf) {
        int r0 = kbase + kt * 16 + kk0, r1 = kbase + kt * 16 + kk1;
        uint base = abase + (uint)buf * (CSTAGEW * 4);
        cp16(base + (uint)(kk0 * 136 + m4) * 4, &A[(size_t)r0 * C_ + m0 + m4]);
        cp16(base + (uint)(kk1 * 136 + m4) * 4, &A[(size_t)r1 * C_ + m0 + m4]);
        cp16(base + (uint)(16 * 136 + kk0 * 136 + m4) * 4, &Bx[(size_t)r0 * C_ + n0 + m4]);
        cp16(base + (uint)(16 * 136 + kk1 * 136 + m4) * 4, &Bx[(size_t)r1 * C_ + n0 + m4]);
        CP_COMMIT();
    };

    const int NT = CHK_ / 16;   // 72
    ISSUE(0, 0);
    ISSUE(1, 1);
    for (int kt = 0; kt < NT; kt++) {
        if (kt < NT - 1) { CP_WAIT1(); } else { CP_WAIT0(); }
        __syncthreads();
        if (kt + 2 < NT) ISSUE(kt + 2, (kt + 2) % 3);
        const uint* sa = cpool + (kt % 3) * CSTAGEW;
        const uint* sb = sa + 16 * 136;
        #pragma unroll
        for (int ks = 0; ks < 16; ks += 8) {
            uint afr[4][4], bfr[4][2];
            #pragma unroll
            for (int mt = 0; mt < 4; mt++) {
                int m = wm + mt * 16 + g;
                afr[mt][0] = sa[(ks + tg) * 136 + m];
                afr[mt][1] = sa[(ks + tg) * 136 + m + 8];
                afr[mt][2] = sa[(ks + tg + 4) * 136 + m];
                afr[mt][3] = sa[(ks + tg + 4) * 136 + m + 8];
            }
            #pragma unroll
            for (int nt = 0; nt < 4; nt++) {
                int n = wn + nt * 8 + g;
                bfr[nt][0] = sb[(ks + tg) * 136 + n];
                bfr[nt][1] = sb[(ks + tg + 4) * 136 + n];
            }
            #pragma unroll
            for (int mt = 0; mt < 4; mt++)
                #pragma unroll
                for (int nt = 0; nt < 4; nt++)
                    mma8(acc[mt][nt], afr[mt], bfr[nt]);
        }
    }

    float* dst = ctxp + ((size_t)sk * B_ + b) * C_ * C_;
    #pragma unroll
    for (int mt = 0; mt < 4; mt++) {
        int row = m0 + wm + mt * 16 + g;
        #pragma unroll
        for (int nt = 0; nt < 4; nt++) {
            int col = n0 + wn + nt * 8 + tg * 2;
            *(float2*)&dst[(size_t)row * C_ + col] = make_float2(acc[mt][nt].x, acc[mt][nt].y);
            *(float2*)&dst[(size_t)(row + 8) * C_ + col] = make_float2(acc[mt][nt].z, acc[mt][nt].w);
        }
    }
}

// ---------------- combined 4-way top-k masked softmax (64-bit key ranks) ------
__global__ void topk_kernel(const float* __restrict__ ctxp, float* __restrict__ ctx,
                            const float* __restrict__ aw, const float* __restrict__ Sg) {
    __shared__ ull sk_[C_];
    __shared__ float shm[1];
    __shared__ float s4[4][8];
    int row = blockIdx.x;
    int b = row >> 8, d = row & 255;
    int t = threadIdx.x;
    float v = 0.f;
    #pragma unroll
    for (int sk = 0; sk < KS_; sk++)
        v += ctxp[(((size_t)sk * B_ + b) * C_ + d) * C_ + t];
    v /= Sg[row];

    // sortable key: value-order in high 32 bits, reverse index low (ties -> lower idx wins)
    uint bits = __float_as_uint(v);
    uint su = bits ^ ((uint)((int)bits >> 31) | 0x80000000u);
    ull key = ((ull)su << 32) | (uint)(C_ - 1 - t);
    sk_[t] = key;
    __syncthreads();

    int rank = 0;
    #pragma unroll 8
    for (int f = 0; f < C_; f++) rank += (sk_[f] > key);

    if (rank == 0) shm[0] = v;   // the max element
    __syncthreads();
    float m = shm[0];
    float e = fexp(v - m);

    float z1 = (rank < 128) ? e : 0.f;
    float z2 = (rank < 170) ? e : 0.f;
    float z3 = (rank < 192) ? e : 0.f;
    float z4 = (rank < 204) ? e : 0.f;
    #pragma unroll
    for (int o = 16; o > 0; o >>= 1) {
        z1 += __shfl_xor_sync(0xffffffffu, z1, o);
        z2 += __shfl_xor_sync(0xffffffffu, z2, o);
        z3 += __shfl_xor_sync(0xffffffffu, z3, o);
        z4 += __shfl_xor_sync(0xffffffffu, z4, o);
    }
    int warp = t >> 5;
    if ((t & 31) == 0) {
        s4[0][warp] = z1; s4[1][warp] = z2; s4[2][warp] = z3; s4[3][warp] = z4;
    }
    __syncthreads();
    float Z1 = 0.f, Z2 = 0.f, Z3 = 0.f, Z4 = 0.f;
    #pragma unroll
    for (int wq = 0; wq < 8; wq++) {
        Z1 += s4[0][wq]; Z2 += s4[1][wq]; Z3 += s4[2][wq]; Z4 += s4[3][wq];
    }
    float coeff = 0.f;
    if (rank < 128) coeff += aw[0] / Z1;
    if (rank < 170) coeff += aw[1] / Z2;
    if (rank < 192) coeff += aw[2] / Z3;
    if (rank < 204) coeff += aw[3] / Z4;
    ctx[(size_t)row * C_ + t] = e * coeff;
}

// ---------------- small GEMM (F1): WA = tf32(reproj_w @ A) --------------------
__global__ void gemm64(const float* __restrict__ A, const float* __restrict__ B,
                       float* __restrict__ C,
                       int K, size_t sA, size_t sB, size_t sC,
                       int lda, int ldb, int ldc) {
    int bz = blockIdx.z;
    const float* Ab = A + (size_t)bz * sA;
    const float* Bb = B + (size_t)bz * sB;
    float* Cb = C + (size_t)bz * sC;
    int m0 = blockIdx.y * 64, n0 = blockIdx.x * 64;
    __shared__ float sa[16][65];
    __shared__ float sb[16][64];
    int t = threadIdx.x;
    int tx = t % 16, ty = t / 16;
    int r_ld = t / 16, kk_lda = t % 16;
    int c_ld = t % 64, kk_ldb = t / 64;
    float acc[4][4] = {};
    for (int k0 = 0; k0 < K; k0 += 16) {
        __syncthreads();
        #pragma unroll
        for (int it = 0; it < 4; it++) {
            sa[kk_lda][r_ld + 16 * it] = Ab[(size_t)(m0 + r_ld + 16 * it) * lda + k0 + kk_lda];
            sb[kk_ldb + 4 * it][c_ld] = Bb[(size_t)(k0 + kk_ldb + 4 * it) * ldb + n0 + c_ld];
        }
        __syncthreads();
        #pragma unroll
        for (int kk = 0; kk < 16; kk++) {
            float av[4], bv[4];
            #pragma unroll
            for (int i = 0; i < 4; i++) av[i] = sa[kk][ty + 16 * i];
            #pragma unroll
            for (int j = 0; j < 4; j++) bv[j] = sb[kk][tx + 16 * j];
            #pragma unroll
            for (int i = 0; i < 4; i++)
                #pragma unroll
                for (int j = 0; j < 4; j++) acc[i][j] = fmaf(av[i], bv[j], acc[i][j]);
        }
    }
    #pragma unroll
    for (int i = 0; i < 4; i++)
        #pragma unroll
        for (int j = 0; j < 4; j++)
            Cb[(size_t)(m0 + ty + 16 * i) * ldc + n0 + tx + 16 * j] = tf32f(acc[i][j]);
}

// ---------------- final: rp = (qe @ WA^T)/qs + bias -> LN -> NCHW -------------
#define FSTAGEW ((64 + 512) * 8)          // words per k8 stage = 4608
#define FSMEM   (3 * FSTAGEW * 4)         // 55296 B
__global__ __launch_bounds__(512) void final_kernel(
        const float* __restrict__ qe, const float* __restrict__ qsg,
        const float* __restrict__ WA,
        const float* __restrict__ rbias, const float* __restrict__ w2g,
        const float* __restrict__ b2g, float* __restrict__ out) {
    extern __shared__ __align__(16) uint pool[];

    int bb = blockIdx.y;
    int n0 = blockIdx.x * 64;
    const float* qb  = qe + (size_t)bb * N_ * C_ + (size_t)n0 * C_;
    const float* WAb = WA + (size_t)bb * O_ * C_;

    int t = threadIdx.x, warp = t >> 5, lane = t & 31, g = lane >> 2, tg = lane & 3;
    int o0 = warp * 32;
    uint abase = smem_u32(pool);

    float4 acc[4][4];
    #pragma unroll
    for (int i = 0; i < 4; i++)
        #pragma unroll
        for (int j = 0; j < 4; j++) acc[i][j] = make_float4(0.f, 0.f, 0.f, 0.f);

    auto ISSUE = [&](int kt, int buf) {
        int k0 = kt * 8;
        uint base = abase + (uint)buf * (FSTAGEW * 4);
        #pragma unroll
        for (int i = 0; i < 3; i++) {
            int c = t + 512 * i;
            if (i < 2 || t < 128) {
                int row = c >> 1, half = c & 1;
                const float* src = (row < 64)
                    ? &qb[(size_t)row * C_ + k0 + half * 4]
                    : &WAb[(size_t)(row - 64) * C_ + k0 + half * 4];
                cp16(base + (uint)(row * 8 + half * 4) * 4, src);
            }
        }
        CP_COMMIT();
    };

    const int NT = C_ / 8;   // 32
    ISSUE(0, 0);
    ISSUE(1, 1);
    for (int kt = 0; kt < NT; kt++) {
        if (kt < NT - 1) { CP_WAIT1(); } else { CP_WAIT0(); }
        __syncthreads();
        if (kt + 2 < NT) ISSUE(kt + 2, (kt + 2) % 3);
        const uint* sq  = pool + (kt % 3) * FSTAGEW;
        const uint* swa = sq + 64 * 8;
        uint afr[4][4], bfr[4][2];
        #pragma unroll
        for (int mt = 0; mt < 4; mt++) {
            int r1 = mt * 16 + g;
            afr[mt][0] = sq[r1 * 8 + tg];
            afr[mt][1] = sq[(r1 + 8) * 8 + tg];
            afr[mt][2] = sq[r1 * 8 + tg + 4];
            afr[mt][3] = sq[(r1 + 8) * 8 + tg + 4];
        }
        #pragma unroll
        for (int nt = 0; nt < 4; nt++) {
            int o = o0 + nt * 8 + g;
            bfr[nt][0] = swa[o * 8 + tg];
            bfr[nt][1] = swa[o * 8 + tg + 4];
        }
        #pragma unroll
        for (int mt = 0; mt < 4; mt++)
            #pragma unroll
            for (int nt = 0; nt < 4; nt++)
                mma8(acc[mt][nt], afr[mt], bfr[nt]);
    }
    __syncthreads();

    // ---- epilogue (pool reused) ----
    float* redS = (float*)pool;            // [16][64]
    float* redQ = (float*)(pool + 1024);   // [16][64]
    float* muS  = (float*)(pool + 2048);   // [64]
    float* rsS  = (float*)(pool + 2112);   // [64]
    float* sout = (float*)(pool + 2176);   // [128][68]

    const float* qsb = qsg + (size_t)bb * N_ + n0;
    float i1[4], i2[4];
    #pragma unroll
    for (int mt = 0; mt < 4; mt++) {
        i1[mt] = 1.f / qsb[mt * 16 + g];
        i2[mt] = 1.f / qsb[mt * 16 + g + 8];
    }
    #pragma unroll
    for (int nt = 0; nt < 4; nt++) {
        int o = o0 + nt * 8 + tg * 2;
        float2 rb = *(const float2*)&rbias[o];
        #pragma unroll
        for (int mt = 0; mt < 4; mt++) {
            acc[mt][nt].x = acc[mt][nt].x * i1[mt] + rb.x;
            acc[mt][nt].y = acc[mt][nt].y * i1[mt] + rb.y;
            acc[mt][nt].z = acc[mt][nt].z * i2[mt] + rb.x;
            acc[mt][nt].w = acc[mt][nt].w * i2[mt] + rb.y;
        }
    }

    #pragma unroll
    for (int mt = 0; mt < 4; mt++) {
        float sA = 0.f, qA = 0.f, sB = 0.f, qB = 0.f;
        #pragma unroll
        for (int nt = 0; nt < 4; nt++) {
            float4 a = acc[mt][nt];
            sA += a.x + a.y; qA += a.x * a.x + a.y * a.y;
            sB += a.z + a.w; qB += a.z * a.z + a.w * a.w;
        }
        #pragma unroll
        for (int o = 1; o <= 2; o <<= 1) {
            sA += __shfl_xor_sync(0xffffffffu, sA, o);
            qA += __shfl_xor_sync(0xffffffffu, qA, o);
            sB += __shfl_xor_sync(0xffffffffu, sB, o);
            qB += __shfl_xor_sync(0xffffffffu, qB, o);
        }
        if (tg == 0) {
            redS[warp * 64 + mt * 16 + g] = sA;
            redQ[warp * 64 + mt * 16 + g] = qA;
            redS[warp * 64 + mt * 16 + g + 8] = sB;
            redQ[warp * 64 + mt * 16 + g + 8] = qB;
        }
    }
    __syncthreads();
    if (t < 64) {
        float s = 0.f, qq = 0.f;
        #pragma unroll
        for (int w = 0; w < 16; w++) { s += redS[w * 64 + t]; qq += redQ[w * 64 + t]; }
        float mu = s * (1.f / O_);
        float var = qq * (1.f / O_) - mu * mu;
        muS[t] = mu;
        rsS[t] = rsqrtf(var + LN_EPS);
    }
    __syncthreads();
    float mu1[4], rs1[4], mu2[4], rs2[4];
    #pragma unroll
    for (int mt = 0; mt < 4; mt++) {
        mu1[mt] = muS[mt * 16 + g];     rs1[mt] = rsS[mt * 16 + g];
        mu2[mt] = muS[mt * 16 + g + 8]; rs2[mt] = rsS[mt * 16 + g + 8];
    }
    __syncthreads();

    #pragma unroll
    for (int p = 0; p < 4; p++) {
        if ((warp >> 2) == p) {
            int obase = (warp & 3) * 32;
            #pragma unroll
            for (int nt = 0; nt < 4; nt++) {
                int ol = obase + nt * 8 + tg * 2;
                int o = p * 128 + ol;
                float2 wv = *(const float2*)&w2g[o];
                float2 bv = *(const float2*)&b2g[o];
                #pragma unroll
                for (int mt = 0; mt < 4; mt++) {
                    int r1 = mt * 16 + g, r2 = r1 + 8;
                    float4 a = acc[mt][nt];
                    sout[ol * 68 + r1]       = (a.x - mu1[mt]) * rs1[mt] * wv.x + bv.x;
                    sout[(ol + 1) * 68 + r1] = (a.y - mu1[mt]) * rs1[mt] * wv.y + bv.y;
                    sout[ol * 68 + r2]       = (a.z - mu2[mt]) * rs2[mt] * wv.x + bv.x;
                    sout[(ol + 1) * 68 + r2] = (a.w - mu2[mt]) * rs2[mt] * wv.y + bv.y;
                }
            }
        }
        __syncthreads();
        #pragma unroll
        for (int i = 0; i < 4; i++) {
            int idx = t + 512 * i;
            int ol = idx >> 4, nn = (idx & 15) * 4;
            float4 v = *(float4*)&sout[ol * 68 + nn];
            *(float4*)&out[((size_t)bb * O_ + p * 128 + ol) * N_ + n0 + nn] = v;
        }
        __syncthreads();
    }
}

// ---------------- launch -----------------------------------------------------
extern "C" void kernel_launch(void* const* d_in, const int* in_sizes, int n_in,
                              void* d_out, int out_size) {
    const float* x1       = (const float*)d_in[0];
    const float* x2       = (const float*)d_in[1];
    const float* norm1_w  = (const float*)d_in[2];
    const float* norm1_b  = (const float*)d_in[3];
    const float* reproj_w = (const float*)d_in[4];
    const float* reproj_b = (const float*)d_in[5];
    const float* norm2_w  = (const float*)d_in[6];
    const float* norm2_b  = (const float*)d_in[7];
    const float* attn_w   = (const float*)d_in[8];
    float* out = (float*)d_out;

    float *qe, *qs, *n1, *S, *ctxp, *ctx, *WA;
    cudaGetSymbolAddress((void**)&qe,   g_qe);
    cudaGetSymbolAddress((void**)&qs,   g_qs);
    cudaGetSymbolAddress((void**)&n1,   g_n1);
    cudaGetSymbolAddress((void**)&S,    g_S);
    cudaGetSymbolAddress((void**)&ctxp, g_ctxp);
    cudaGetSymbolAddress((void**)&ctx,  g_ctx);
    cudaGetSymbolAddress((void**)&WA,   g_WA);

    cudaFuncSetAttribute(ctx_gemm,
                         cudaFuncAttributeMaxDynamicSharedMemorySize, CSMEM);
    cudaFuncSetAttribute(final_kernel,
                         cudaFuncAttributeMaxDynamicSharedMemorySize, FSMEM);

    prod_kernel<<<dim3(B_ * N_ / 8, 2), 256>>>(x1, x2, norm1_w, norm1_b, n1, qe, qs);
    zero_kernel<<<(B_ * C_ + 255) / 256, 256>>>(S, B_ * C_);
    colsum_kernel<<<dim3(NCH_, B_), 256>>>(qe, S);

    ctx_gemm<<<dim3(2, 2, B_ * KS_), 256, CSMEM>>>(qe, n1, ctxp);

    topk_kernel<<<B_ * C_, 256>>>(ctxp, ctx, attn_w, S);

    gemm64<<<dim3(C_ / 64, O_ / 64, B_), 256>>>(
        reproj_w, ctx, WA, C_,
        (size_t)0, (size_t)C_ * C_, (size_t)O_ * C_,
        C_, C_, C_);

    final_kernel<<<dim3(N_ / 64, B_), 512, FSMEM>>>(
        qe, qs, WA, reproj_b, norm2_w, norm2_b, out);
}

// round 14
// speedup vs baseline: 1.6015x; 1.5322x over previous
#include <cuda_runtime.h>
#include <cuda_fp16.h>
#include <math.h>

#define B_ 8
#define N_ 9216
#define C_ 256
#define O_ 512
#define KS_ 8
#define CHK_ (N_/KS_)      // 1152
#define NCH_ 72
#define CR_ 128
#define LN_EPS 1e-5f

typedef unsigned int uint;
typedef unsigned long long ull;

// ---------------- scratch ----------------------------------------------------
__device__ __half g_qe [B_*N_*C_];   // fp16 unnormalized exp(LN(x2))
__device__ float  g_qs [B_*N_];      // channel sum-exp per row (fp32)
__device__ __half g_n1 [B_*N_*C_];   // fp16 LN(x1)
__device__ float  g_S  [B_*C_];      // N-softmax denom per (b,d)
__device__ float  g_ctxp[(size_t)KS_*B_*C_*C_];
__device__ float  g_ctx[B_*C_*C_];
__device__ __half g_WA [B_*O_*C_];   // fp16

// ---------------- fast exp (FMA only) ----------------------------------------
__device__ __forceinline__ float fexp(float x) {
    float t = fmaf(x, 1.4426950408889634f, 12582912.0f);
    float n = t - 12582912.0f;
    int ni = __float_as_int(t) - 0x4B400000;
    float r = fmaf(n, -0.693359375f, x);
    r = fmaf(n, 2.12194440e-4f, r);
    float z = r * r;
    float p = 1.9875691500E-4f;
    p = fmaf(p, r, 1.3981999507E-3f);
    p = fmaf(p, r, 8.3334519073E-3f);
    p = fmaf(p, r, 4.1665795894E-2f);
    p = fmaf(p, r, 1.6666665459E-1f);
    p = fmaf(p, r, 5.0000001201E-1f);
    float res = fmaf(z, p, r) + 1.0f;
    res = __int_as_float(__float_as_int(res) + (ni << 23));
    return (x > -80.0f) ? res : 0.0f;
}

// ---------------- mma / ldmatrix helpers ---------------------------------------
__device__ __forceinline__ void mma16(float4& d, const uint* a, const uint* b) {
    asm volatile("mma.sync.aligned.m16n8k16.row.col.f32.f16.f16.f32 "
        "{%0,%1,%2,%3}, {%4,%5,%6,%7}, {%8,%9}, {%0,%1,%2,%3};"
        : "+f"(d.x), "+f"(d.y), "+f"(d.z), "+f"(d.w)
        : "r"(a[0]), "r"(a[1]), "r"(a[2]), "r"(a[3]), "r"(b[0]), "r"(b[1]));
}
__device__ __forceinline__ void ldsm4t(uint* r, uint addr) {
    asm volatile("ldmatrix.sync.aligned.m8n8.x4.trans.shared.b16 {%0,%1,%2,%3}, [%4];"
        : "=r"(r[0]), "=r"(r[1]), "=r"(r[2]), "=r"(r[3]) : "r"(addr));
}
__device__ __forceinline__ void ldsm2t(uint* r, uint addr) {
    asm volatile("ldmatrix.sync.aligned.m8n8.x2.trans.shared.b16 {%0,%1}, [%2];"
        : "=r"(r[0]), "=r"(r[1]) : "r"(addr));
}
__device__ __forceinline__ void ldsm4(uint* r, uint addr) {
    asm volatile("ldmatrix.sync.aligned.m8n8.x4.shared.b16 {%0,%1,%2,%3}, [%4];"
        : "=r"(r[0]), "=r"(r[1]), "=r"(r[2]), "=r"(r[3]) : "r"(addr));
}
__device__ __forceinline__ void ldsm2(uint* r, uint addr) {
    asm volatile("ldmatrix.sync.aligned.m8n8.x2.shared.b16 {%0,%1}, [%2];"
        : "=r"(r[0]), "=r"(r[1]) : "r"(addr));
}
__device__ __forceinline__ uint smem_u32(const void* p) {
    uint a;
    asm("{ .reg .u64 t; cvta.to.shared.u64 t, %1; cvt.u32.u64 %0, t; }"
        : "=r"(a) : "l"(p));
    return a;
}
__device__ __forceinline__ void cp16(uint dst, const void* src) {
    asm volatile("cp.async.cg.shared.global [%0], [%1], 16;"
                 :: "r"(dst), "l"(src) : "memory");
}
#define CP_COMMIT() asm volatile("cp.async.commit_group;" ::: "memory")
#define CP_WAIT1()  asm volatile("cp.async.wait_group 1;" ::: "memory")
#define CP_WAIT0()  asm volatile("cp.async.wait_group 0;" ::: "memory")

// ---------------- merged producers: y=0 -> n1; y=1 -> qe/qs --------------------
__global__ void prod_kernel(const float* __restrict__ x1,
                            const float* __restrict__ x2,
                            const float* __restrict__ w,
                            const float* __restrict__ b,
                            __half* __restrict__ n1,
                            __half* __restrict__ qe,
                            float* __restrict__ qs) {
    int warp = threadIdx.x >> 5, lane = threadIdx.x & 31;
    size_t row = (size_t)blockIdx.x * 8 + warp;
    const float* x = (blockIdx.y == 0) ? x1 : x2;
    const float4* xr = (const float4*)(x + row * C_);
    float4 v0 = xr[lane], v1 = xr[lane + 32];
    float s  = v0.x + v0.y + v0.z + v0.w + v1.x + v1.y + v1.z + v1.w;
    float s2 = v0.x*v0.x + v0.y*v0.y + v0.z*v0.z + v0.w*v0.w
             + v1.x*v1.x + v1.y*v1.y + v1.z*v1.z + v1.w*v1.w;
    #pragma unroll
    for (int o = 16; o > 0; o >>= 1) {
        s  += __shfl_xor_sync(0xffffffffu, s, o);
        s2 += __shfl_xor_sync(0xffffffffu, s2, o);
    }
    float mu = s * (1.f / C_);
    float rsd = rsqrtf(s2 * (1.f / C_) - mu * mu + LN_EPS);
    float4 w0 = ((const float4*)w)[lane], w1 = ((const float4*)w)[lane + 32];
    float4 b0 = ((const float4*)b)[lane], b1 = ((const float4*)b)[lane + 32];
    float4 l0, l1;
    l0.x = (v0.x - mu) * rsd * w0.x + b0.x;
    l0.y = (v0.y - mu) * rsd * w0.y + b0.y;
    l0.z = (v0.z - mu) * rsd * w0.z + b0.z;
    l0.w = (v0.w - mu) * rsd * w0.w + b0.w;
    l1.x = (v1.x - mu) * rsd * w1.x + b1.x;
    l1.y = (v1.y - mu) * rsd * w1.y + b1.y;
    l1.z = (v1.z - mu) * rsd * w1.z + b1.z;
    l1.w = (v1.w - mu) * rsd * w1.w + b1.w;
    if (blockIdx.y == 0) {
        __half2* outr = (__half2*)(n1 + row * C_);
        outr[lane * 2]      = __floats2half2_rn(l0.x, l0.y);
        outr[lane * 2 + 1]  = __floats2half2_rn(l0.z, l0.w);
        outr[64 + lane * 2] = __floats2half2_rn(l1.x, l1.y);
        outr[65 + lane * 2] = __floats2half2_rn(l1.z, l1.w);
    } else {
        float4 e0, e1;
        e0.x = fexp(l0.x); e0.y = fexp(l0.y); e0.z = fexp(l0.z); e0.w = fexp(l0.w);
        e1.x = fexp(l1.x); e1.y = fexp(l1.y); e1.z = fexp(l1.z); e1.w = fexp(l1.w);
        float se = e0.x + e0.y + e0.z + e0.w + e1.x + e1.y + e1.z + e1.w;
        #pragma unroll
        for (int o = 16; o > 0; o >>= 1) se += __shfl_xor_sync(0xffffffffu, se, o);
        __half2* qer = (__half2*)(qe + row * C_);
        qer[lane * 2]      = __floats2half2_rn(e0.x, e0.y);
        qer[lane * 2 + 1]  = __floats2half2_rn(e0.z, e0.w);
        qer[64 + lane * 2] = __floats2half2_rn(e1.x, e1.y);
        qer[65 + lane * 2] = __floats2half2_rn(e1.z, e1.w);
        if (lane == 0) qs[row] = se;
    }
}

// ---------------- zero + column sum (S) ----------------------------------------
__global__ void zero_kernel(float* __restrict__ p, int n) {
    int i = blockIdx.x * 256 + threadIdx.x;
    if (i < n) p[i] = 0.f;
}
__global__ void colsum_kernel(const __half* __restrict__ qe, float* __restrict__ S) {
    int b = blockIdx.y, ch = blockIdx.x, t = threadIdx.x;
    const __half* base = qe + ((size_t)b * N_ + (size_t)ch * CR_) * C_ + t;
    float s = 0.f;
    #pragma unroll 8
    for (int r = 0; r < CR_; r++) s += __half2float(base[(size_t)r * C_]);
    atomicAdd(&S[b * C_ + t], s);
}

// ---------------- context GEMM: fp16 mma + ldmatrix, cp.async 3-stage ----------
#define CROW 136                       // halves per smem row (272B, bank-clean)
#define CAB  (16 * CROW * 2)           // bytes per operand tile = 4352
#define CSTAGEB (2 * CAB)              // 8704 B per stage
__global__ __launch_bounds__(256) void ctx_gemm(
        const __half* __restrict__ qe, const __half* __restrict__ n1,
        float* __restrict__ ctxp) {
    __shared__ __align__(16) __half cbuf[3 * CSTAGEB / 2];
    int bz = blockIdx.z;
    int b = bz / KS_, sk = bz % KS_;
    int m0 = blockIdx.y * 128, n0 = blockIdx.x * 128;
    const __half* A  = qe + (size_t)b * N_ * C_;
    const __half* Bx = n1 + (size_t)b * N_ * C_;

    int t = threadIdx.x;
    int warp = t >> 5, lane = t & 31;
    int g = lane >> 2, tg = lane & 3;
    int wm = (warp >> 2) * 64, wn = (warp & 3) * 32;
    int l8 = lane & 7, grp = lane >> 3, grpB = grp & 1;
    int ldr = t >> 4, ldc = t & 15;     // loader: row 0..15, chunk 0..15
    int kbase = sk * CHK_;
    uint cbase = smem_u32(cbuf);

    // ldmatrix offsets (bytes within a stage)
    uint aoff[4], boff[4];
    #pragma unroll
    for (int mt = 0; mt < 4; mt++)
        aoff[mt] = (uint)(((l8 + (grp >> 1) * 8) * CROW + wm + mt * 16 + (grp & 1) * 8) * 2);
    #pragma unroll
    for (int nt = 0; nt < 4; nt++)
        boff[nt] = (uint)(((l8 + grpB * 8) * CROW + wn + nt * 8) * 2) + CAB;

    float4 acc[4][4];
    #pragma unroll
    for (int i = 0; i < 4; i++)
        #pragma unroll
        for (int j = 0; j < 4; j++) acc[i][j] = make_float4(0.f, 0.f, 0.f, 0.f);

    auto ISSUE = [&](int kt, int buf) {
        int rg = kbase + kt * 16 + ldr;
        uint base = cbase + (uint)buf * CSTAGEB;
        cp16(base + (uint)((ldr * CROW + ldc * 8) * 2), &A[(size_t)rg * C_ + m0 + ldc * 8]);
        cp16(base + CAB + (uint)((ldr * CROW + ldc * 8) * 2), &Bx[(size_t)rg * C_ + n0 + ldc * 8]);
        CP_COMMIT();
    };

    const int NT = CHK_ / 16;   // 72
    ISSUE(0, 0);
    ISSUE(1, 1);
    for (int kt = 0; kt < NT; kt++) {
        if (kt < NT - 1) { CP_WAIT1(); } else { CP_WAIT0(); }
        __syncthreads();
        if (kt + 2 < NT) ISSUE(kt + 2, (kt + 2) % 3);
        uint sbase = cbase + (uint)(kt % 3) * CSTAGEB;
        uint a[4][4], bf[4][2];
        #pragma unroll
        for (int mt = 0; mt < 4; mt++) ldsm4t(a[mt], sbase + aoff[mt]);
        #pragma unroll
        for (int nt = 0; nt < 4; nt++) ldsm2t(bf[nt], sbase + boff[nt]);
        #pragma unroll
        for (int mt = 0; mt < 4; mt++)
            #pragma unroll
            for (int nt = 0; nt < 4; nt++)
                mma16(acc[mt][nt], a[mt], bf[nt]);
    }

    float* dst = ctxp + ((size_t)sk * B_ + b) * C_ * C_;
    #pragma unroll
    for (int mt = 0; mt < 4; mt++) {
        int row = m0 + wm + mt * 16 + g;
        #pragma unroll
        for (int nt = 0; nt < 4; nt++) {
            int col = n0 + wn + nt * 8 + tg * 2;
            *(float2*)&dst[(size_t)row * C_ + col] = make_float2(acc[mt][nt].x, acc[mt][nt].y);
            *(float2*)&dst[(size_t)(row + 8) * C_ + col] = make_float2(acc[mt][nt].z, acc[mt][nt].w);
        }
    }
}

// ---------------- combined 4-way top-k masked softmax (64-bit key ranks) -------
__global__ void topk_kernel(const float* __restrict__ ctxp, float* __restrict__ ctx,
                            const float* __restrict__ aw, const float* __restrict__ Sg) {
    __shared__ ull sk_[C_];
    __shared__ float shm[1];
    __shared__ float s4[4][8];
    int row = blockIdx.x;
    int b = row >> 8, d = row & 255;
    int t = threadIdx.x;
    float v = 0.f;
    #pragma unroll
    for (int sk = 0; sk < KS_; sk++)
        v += ctxp[(((size_t)sk * B_ + b) * C_ + d) * C_ + t];
    v /= Sg[row];

    uint bits = __float_as_uint(v);
    uint su = bits ^ ((uint)((int)bits >> 31) | 0x80000000u);
    ull key = ((ull)su << 32) | (uint)(C_ - 1 - t);
    sk_[t] = key;
    __syncthreads();

    int rank = 0;
    #pragma unroll 8
    for (int f = 0; f < C_; f++) rank += (sk_[f] > key);

    if (rank == 0) shm[0] = v;
    __syncthreads();
    float m = shm[0];
    float e = fexp(v - m);

    float z1 = (rank < 128) ? e : 0.f;
    float z2 = (rank < 170) ? e : 0.f;
    float z3 = (rank < 192) ? e : 0.f;
    float z4 = (rank < 204) ? e : 0.f;
    #pragma unroll
    for (int o = 16; o > 0; o >>= 1) {
        z1 += __shfl_xor_sync(0xffffffffu, z1, o);
        z2 += __shfl_xor_sync(0xffffffffu, z2, o);
        z3 += __shfl_xor_sync(0xffffffffu, z3, o);
        z4 += __shfl_xor_sync(0xffffffffu, z4, o);
    }
    int warp = t >> 5;
    if ((t & 31) == 0) {
        s4[0][warp] = z1; s4[1][warp] = z2; s4[2][warp] = z3; s4[3][warp] = z4;
    }
    __syncthreads();
    float Z1 = 0.f, Z2 = 0.f, Z3 = 0.f, Z4 = 0.f;
    #pragma unroll
    for (int wq = 0; wq < 8; wq++) {
        Z1 += s4[0][wq]; Z2 += s4[1][wq]; Z3 += s4[2][wq]; Z4 += s4[3][wq];
    }
    float coeff = 0.f;
    if (rank < 128) coeff += aw[0] / Z1;
    if (rank < 170) coeff += aw[1] / Z2;
    if (rank < 192) coeff += aw[2] / Z3;
    if (rank < 204) coeff += aw[3] / Z4;
    ctx[(size_t)row * C_ + t] = e * coeff;
}

// ---------------- small GEMM (F1): WA = fp16(reproj_w @ A) ---------------------
__global__ void gemm64(const float* __restrict__ A, const float* __restrict__ B,
                       __half* __restrict__ C,
                       int K, size_t sA, size_t sB, size_t sC,
                       int lda, int ldb, int ldc) {
    int bz = blockIdx.z;
    const float* Ab = A + (size_t)bz * sA;
    const float* Bb = B + (size_t)bz * sB;
    __half* Cb = C + (size_t)bz * sC;
    int m0 = blockIdx.y * 64, n0 = blockIdx.x * 64;
    __shared__ float sa[16][65];
    __shared__ float sb[16][64];
    int t = threadIdx.x;
    int tx = t % 16, ty = t / 16;
    int r_ld = t / 16, kk_lda = t % 16;
    int c_ld = t % 64, kk_ldb = t / 64;
    float acc[4][4] = {};
    for (int k0 = 0; k0 < K; k0 += 16) {
        __syncthreads();
        #pragma unroll
        for (int it = 0; it < 4; it++) {
            sa[kk_lda][r_ld + 16 * it] = Ab[(size_t)(m0 + r_ld + 16 * it) * lda + k0 + kk_lda];
            sb[kk_ldb + 4 * it][c_ld] = Bb[(size_t)(k0 + kk_ldb + 4 * it) * ldb + n0 + c_ld];
        }
        __syncthreads();
        #pragma unroll
        for (int kk = 0; kk < 16; kk++) {
            float av[4], bv[4];
            #pragma unroll
            for (int i = 0; i < 4; i++) av[i] = sa[kk][ty + 16 * i];
            #pragma unroll
            for (int j = 0; j < 4; j++) bv[j] = sb[kk][tx + 16 * j];
            #pragma unroll
            for (int i = 0; i < 4; i++)
                #pragma unroll
                for (int j = 0; j < 4; j++) acc[i][j] = fmaf(av[i], bv[j], acc[i][j]);
        }
    }
    #pragma unroll
    for (int i = 0; i < 4; i++)
        #pragma unroll
        for (int j = 0; j < 4; j++)
            Cb[(size_t)(m0 + ty + 16 * i) * ldc + n0 + tx + 16 * j] = __float2half_rn(acc[i][j]);
}

// ---------------- final: rp = (qe @ WA^T)/qs + bias -> LN -> NCHW (fp16 mma) ---
#define FROW 24                         // halves per smem row (48B, bank-clean)
#define FSTAGEB ((64 + 512) * FROW * 2) // 27648 B per k16 stage
#define FSMEM   (3 * FSTAGEB)           // 82944 B
__global__ __launch_bounds__(512) void final_kernel(
        const __half* __restrict__ qe, const float* __restrict__ qsg,
        const __half* __restrict__ WA,
        const float* __restrict__ rbias, const float* __restrict__ w2g,
        const float* __restrict__ b2g, float* __restrict__ out) {
    extern __shared__ __align__(16) uint pool[];

    int bb = blockIdx.y;
    int n0 = blockIdx.x * 64;
    const __half* qb  = qe + (size_t)bb * N_ * C_ + (size_t)n0 * C_;
    const __half* WAb = WA + (size_t)bb * O_ * C_;

    int t = threadIdx.x, warp = t >> 5, lane = t & 31, g = lane >> 2, tg = lane & 3;
    int o0 = warp * 32;
    int l8 = lane & 7, grp = lane >> 3, grpB = grp & 1;
    uint abase = smem_u32(pool);

    // fragment offsets (bytes within a stage); non-trans ldmatrix
    uint aoff[4], boff[4];
    #pragma unroll
    for (int mt = 0; mt < 4; mt++)
        aoff[mt] = (uint)(((mt * 16 + l8 + (grp & 1) * 8) * FROW + (grp >> 1) * 8) * 2);
    #pragma unroll
    for (int nt = 0; nt < 4; nt++)
        boff[nt] = (uint)(((64 + o0 + nt * 8 + l8) * FROW + grpB * 8) * 2);

    float4 acc[4][4];
    #pragma unroll
    for (int i = 0; i < 4; i++)
        #pragma unroll
        for (int j = 0; j < 4; j++) acc[i][j] = make_float4(0.f, 0.f, 0.f, 0.f);

    auto ISSUE = [&](int kt, int buf) {
        int k0 = kt * 16;
        uint base = abase + (uint)buf * FSTAGEB;
        #pragma unroll
        for (int i = 0; i < 3; i++) {
            int c = t + 512 * i;
            if (i < 2 || t < 128) {
                int row = c >> 1, half = c & 1;
                const __half* src = (row < 64)
                    ? &qb[(size_t)row * C_ + k0 + half * 8]
                    : &WAb[(size_t)(row - 64) * C_ + k0 + half * 8];
                cp16(base + (uint)((row * FROW + half * 8) * 2), src);
            }
        }
        CP_COMMIT();
    };

    const int NT = C_ / 16;   // 16
    ISSUE(0, 0);
    ISSUE(1, 1);
    for (int kt = 0; kt < NT; kt++) {
        if (kt < NT - 1) { CP_WAIT1(); } else { CP_WAIT0(); }
        __syncthreads();
        if (kt + 2 < NT) ISSUE(kt + 2, (kt + 2) % 3);
        uint sbase = abase + (uint)(kt % 3) * FSTAGEB;
        uint a[4][4], bf[4][2];
        #pragma unroll
        for (int mt = 0; mt < 4; mt++) ldsm4(a[mt], sbase + aoff[mt]);
        #pragma unroll
        for (int nt = 0; nt < 4; nt++) ldsm2(bf[nt], sbase + boff[nt]);
        #pragma unroll
        for (int mt = 0; mt < 4; mt++)
            #pragma unroll
            for (int nt = 0; nt < 4; nt++)
                mma16(acc[mt][nt], a[mt], bf[nt]);
    }
    __syncthreads();

    // ---- epilogue (pool reused) ----
    float* redS = (float*)pool;            // [16][64]
    float* redQ = (float*)(pool + 1024);   // [16][64]
    float* muS  = (float*)(pool + 2048);   // [64]
    float* rsS  = (float*)(pool + 2112);   // [64]
    float* sout = (float*)(pool + 2176);   // [128][68]

    const float* qsb = qsg + (size_t)bb * N_ + n0;
    float i1[4], i2[4];
    #pragma unroll
    for (int mt = 0; mt < 4; mt++) {
        i1[mt] = 1.f / qsb[mt * 16 + g];
        i2[mt] = 1.f / qsb[mt * 16 + g + 8];
    }
    #pragma unroll
    for (int nt = 0; nt < 4; nt++) {
        int o = o0 + nt * 8 + tg * 2;
        float2 rb = *(const float2*)&rbias[o];
        #pragma unroll
        for (int mt = 0; mt < 4; mt++) {
            acc[mt][nt].x = acc[mt][nt].x * i1[mt] + rb.x;
            acc[mt][nt].y = acc[mt][nt].y * i1[mt] + rb.y;
            acc[mt][nt].z = acc[mt][nt].z * i2[mt] + rb.x;
            acc[mt][nt].w = acc[mt][nt].w * i2[mt] + rb.y;
        }
    }

    #pragma unroll
    for (int mt = 0; mt < 4; mt++) {
        float sA = 0.f, qA = 0.f, sB = 0.f, qB = 0.f;
        #pragma unroll
        for (int nt = 0; nt < 4; nt++) {
            float4 a = acc[mt][nt];
            sA += a.x + a.y; qA += a.x * a.x + a.y * a.y;
            sB += a.z + a.w; qB += a.z * a.z + a.w * a.w;
        }
        #pragma unroll
        for (int o = 1; o <= 2; o <<= 1) {
            sA += __shfl_xor_sync(0xffffffffu, sA, o);
            qA += __shfl_xor_sync(0xffffffffu, qA, o);
            sB += __shfl_xor_sync(0xffffffffu, sB, o);
            qB += __shfl_xor_sync(0xffffffffu, qB, o);
        }
        if (tg == 0) {
            redS[warp * 64 + mt * 16 + g] = sA;
            redQ[warp * 64 + mt * 16 + g] = qA;
            redS[warp * 64 + mt * 16 + g + 8] = sB;
            redQ[warp * 64 + mt * 16 + g + 8] = qB;
        }
    }
    __syncthreads();
    if (t < 64) {
        float s = 0.f, qq = 0.f;
        #pragma unroll
        for (int w = 0; w < 16; w++) { s += redS[w * 64 + t]; qq += redQ[w * 64 + t]; }
        float mu = s * (1.f / O_);
        float var = qq * (1.f / O_) - mu * mu;
        muS[t] = mu;
        rsS[t] = rsqrtf(var + LN_EPS);
    }
    __syncthreads();
    float mu1[4], rs1[4], mu2[4], rs2[4];
    #pragma unroll
    for (int mt = 0; mt < 4; mt++) {
        mu1[mt] = muS[mt * 16 + g];     rs1[mt] = rsS[mt * 16 + g];
        mu2[mt] = muS[mt * 16 + g + 8]; rs2[mt] = rsS[mt * 16 + g + 8];
    }
    __syncthreads();

    #pragma unroll
    for (int p = 0; p < 4; p++) {
        if ((warp >> 2) == p) {
            int obase = (warp & 3) * 32;
            #pragma unroll
            for (int nt = 0; nt < 4; nt++) {
                int ol = obase + nt * 8 + tg * 2;
                int o = p * 128 + ol;
                float2 wv = *(const float2*)&w2g[o];
                float2 bv = *(const float2*)&b2g[o];
                #pragma unroll
                for (int mt = 0; mt < 4; mt++) {
                    int r1 = mt * 16 + g, r2 = r1 + 8;
                    float4 a = acc[mt][nt];
                    sout[ol * 68 + r1]       = (a.x - mu1[mt]) * rs1[mt] * wv.x + bv.x;
                    sout[(ol + 1) * 68 + r1] = (a.y - mu1[mt]) * rs1[mt] * wv.y + bv.y;
                    sout[ol * 68 + r2]       = (a.z - mu2[mt]) * rs2[mt] * wv.x + bv.x;
                    sout[(ol + 1) * 68 + r2] = (a.w - mu2[mt]) * rs2[mt] * wv.y + bv.y;
                }
            }
        }
        __syncthreads();
        #pragma unroll
        for (int i = 0; i < 4; i++) {
            int idx = t + 512 * i;
            int ol = idx >> 4, nn = (idx & 15) * 4;
            float4 v = *(float4*)&sout[ol * 68 + nn];
            *(float4*)&out[((size_t)bb * O_ + p * 128 + ol) * N_ + n0 + nn] = v;
        }
        __syncthreads();
    }
}

// ---------------- launch --------------------------------------------------------
extern "C" void kernel_launch(void* const* d_in, const int* in_sizes, int n_in,
                              void* d_out, int out_size) {
    const float* x1       = (const float*)d_in[0];
    const float* x2       = (const float*)d_in[1];
    const float* norm1_w  = (const float*)d_in[2];
    const float* norm1_b  = (const float*)d_in[3];
    const float* reproj_w = (const float*)d_in[4];
    const float* reproj_b = (const float*)d_in[5];
    const float* norm2_w  = (const float*)d_in[6];
    const float* norm2_b  = (const float*)d_in[7];
    const float* attn_w   = (const float*)d_in[8];
    float* out = (float*)d_out;

    __half *qe, *n1, *WA;
    float *qs, *S, *ctxp, *ctx;
    cudaGetSymbolAddress((void**)&qe,   g_qe);
    cudaGetSymbolAddress((void**)&qs,   g_qs);
    cudaGetSymbolAddress((void**)&n1,   g_n1);
    cudaGetSymbolAddress((void**)&S,    g_S);
    cudaGetSymbolAddress((void**)&ctxp, g_ctxp);
    cudaGetSymbolAddress((void**)&ctx,  g_ctx);
    cudaGetSymbolAddress((void**)&WA,   g_WA);

    cudaFuncSetAttribute(final_kernel,
                         cudaFuncAttributeMaxDynamicSharedMemorySize, FSMEM);

    prod_kernel<<<dim3(B_ * N_ / 8, 2), 256>>>(x1, x2, norm1_w, norm1_b, n1, qe, qs);
    zero_kernel<<<(B_ * C_ + 255) / 256, 256>>>(S, B_ * C_);
    colsum_kernel<<<dim3(NCH_, B_), 256>>>(qe, S);

    ctx_gemm<<<dim3(2, 2, B_ * KS_), 256>>>(qe, n1, ctxp);

    topk_kernel<<<B_ * C_, 256>>>(ctxp, ctx, attn_w, S);

    gemm64<<<dim3(C_ / 64, O_ / 64, B_), 256>>>(
        reproj_w, ctx, WA, C_,
        (size_t)0, (size_t)C_ * C_, (size_t)O_ * C_,
        C_, C_, C_);

    final_kernel<<<dim3(N_ / 64, B_), 512, FSMEM>>>(
        qe, qs, WA, reproj_b, norm2_w, norm2_b, out);
}

// round 15
// speedup vs baseline: 1.8628x; 1.1631x over previous
#include <cuda_runtime.h>
#include <cuda_fp16.h>
#include <math.h>

#define B_ 8
#define N_ 9216
#define C_ 256
#define O_ 512
#define KS_ 8
#define CHK_ (N_/KS_)      // 1152
#define NCH_ 72
#define CR_ 128
#define LN_EPS 1e-5f

typedef unsigned int uint;
typedef unsigned long long ull;

// ---------------- scratch ----------------------------------------------------
__device__ __half g_qe [B_*N_*C_];
__device__ float  g_qs [B_*N_];
__device__ __half g_n1 [B_*N_*C_];
__device__ float  g_S  [B_*C_];
__device__ float  g_ctxp[(size_t)KS_*B_*C_*C_];
__device__ float  g_ctx[B_*C_*C_];
__device__ __half g_WA [B_*O_*C_];

// ---------------- fast exp (FMA only) ----------------------------------------
__device__ __forceinline__ float fexp(float x) {
    float t = fmaf(x, 1.4426950408889634f, 12582912.0f);
    float n = t - 12582912.0f;
    int ni = __float_as_int(t) - 0x4B400000;
    float r = fmaf(n, -0.693359375f, x);
    r = fmaf(n, 2.12194440e-4f, r);
    float z = r * r;
    float p = 1.9875691500E-4f;
    p = fmaf(p, r, 1.3981999507E-3f);
    p = fmaf(p, r, 8.3334519073E-3f);
    p = fmaf(p, r, 4.1665795894E-2f);
    p = fmaf(p, r, 1.6666665459E-1f);
    p = fmaf(p, r, 5.0000001201E-1f);
    float res = fmaf(z, p, r) + 1.0f;
    res = __int_as_float(__float_as_int(res) + (ni << 23));
    return (x > -80.0f) ? res : 0.0f;
}

// ---------------- mma / ldmatrix helpers ---------------------------------------
__device__ __forceinline__ void mma16(float4& d, const uint* a, const uint* b) {
    asm volatile("mma.sync.aligned.m16n8k16.row.col.f32.f16.f16.f32 "
        "{%0,%1,%2,%3}, {%4,%5,%6,%7}, {%8,%9}, {%0,%1,%2,%3};"
        : "+f"(d.x), "+f"(d.y), "+f"(d.z), "+f"(d.w)
        : "r"(a[0]), "r"(a[1]), "r"(a[2]), "r"(a[3]), "r"(b[0]), "r"(b[1]));
}
__device__ __forceinline__ void ldsm4t(uint* r, uint addr) {
    asm volatile("ldmatrix.sync.aligned.m8n8.x4.trans.shared.b16 {%0,%1,%2,%3}, [%4];"
        : "=r"(r[0]), "=r"(r[1]), "=r"(r[2]), "=r"(r[3]) : "r"(addr));
}
__device__ __forceinline__ void ldsm2t(uint* r, uint addr) {
    asm volatile("ldmatrix.sync.aligned.m8n8.x2.trans.shared.b16 {%0,%1}, [%2];"
        : "=r"(r[0]), "=r"(r[1]) : "r"(addr));
}
__device__ __forceinline__ void ldsm4(uint* r, uint addr) {
    asm volatile("ldmatrix.sync.aligned.m8n8.x4.shared.b16 {%0,%1,%2,%3}, [%4];"
        : "=r"(r[0]), "=r"(r[1]), "=r"(r[2]), "=r"(r[3]) : "r"(addr));
}
__device__ __forceinline__ void ldsm2(uint* r, uint addr) {
    asm volatile("ldmatrix.sync.aligned.m8n8.x2.shared.b16 {%0,%1}, [%2];"
        : "=r"(r[0]), "=r"(r[1]) : "r"(addr));
}
__device__ __forceinline__ uint smem_u32(const void* p) {
    uint a;
    asm("{ .reg .u64 t; cvta.to.shared.u64 t, %1; cvt.u32.u64 %0, t; }"
        : "=r"(a) : "l"(p));
    return a;
}
__device__ __forceinline__ void cp16(uint dst, const void* src) {
    asm volatile("cp.async.cg.shared.global [%0], [%1], 16;"
                 :: "r"(dst), "l"(src) : "memory");
}
#define CP_COMMIT() asm volatile("cp.async.commit_group;" ::: "memory")
#define CP_WAIT1()  asm volatile("cp.async.wait_group 1;" ::: "memory")
#define CP_WAIT0()  asm volatile("cp.async.wait_group 0;" ::: "memory")

// ---------------- merged producers --------------------------------------------
__global__ void prod_kernel(const float* __restrict__ x1,
                            const float* __restrict__ x2,
                            const float* __restrict__ w,
                            const float* __restrict__ b,
                            __half* __restrict__ n1,
                            __half* __restrict__ qe,
                            float* __restrict__ qs) {
    int warp = threadIdx.x >> 5, lane = threadIdx.x & 31;
    size_t row = (size_t)blockIdx.x * 8 + warp;
    const float* x = (blockIdx.y == 0) ? x1 : x2;
    const float4* xr = (const float4*)(x + row * C_);
    float4 v0 = xr[lane], v1 = xr[lane + 32];
    float s  = v0.x + v0.y + v0.z + v0.w + v1.x + v1.y + v1.z + v1.w;
    float s2 = v0.x*v0.x + v0.y*v0.y + v0.z*v0.z + v0.w*v0.w
             + v1.x*v1.x + v1.y*v1.y + v1.z*v1.z + v1.w*v1.w;
    #pragma unroll
    for (int o = 16; o > 0; o >>= 1) {
        s  += __shfl_xor_sync(0xffffffffu, s, o);
        s2 += __shfl_xor_sync(0xffffffffu, s2, o);
    }
    float mu = s * (1.f / C_);
    float rsd = rsqrtf(s2 * (1.f / C_) - mu * mu + LN_EPS);
    float4 w0 = ((const float4*)w)[lane], w1 = ((const float4*)w)[lane + 32];
    float4 b0 = ((const float4*)b)[lane], b1 = ((const float4*)b)[lane + 32];
    float4 l0, l1;
    l0.x = (v0.x - mu) * rsd * w0.x + b0.x;
    l0.y = (v0.y - mu) * rsd * w0.y + b0.y;
    l0.z = (v0.z - mu) * rsd * w0.z + b0.z;
    l0.w = (v0.w - mu) * rsd * w0.w + b0.w;
    l1.x = (v1.x - mu) * rsd * w1.x + b1.x;
    l1.y = (v1.y - mu) * rsd * w1.y + b1.y;
    l1.z = (v1.z - mu) * rsd * w1.z + b1.z;
    l1.w = (v1.w - mu) * rsd * w1.w + b1.w;
    if (blockIdx.y == 0) {
        __half2* outr = (__half2*)(n1 + row * C_);
        outr[lane * 2]      = __floats2half2_rn(l0.x, l0.y);
        outr[lane * 2 + 1]  = __floats2half2_rn(l0.z, l0.w);
        outr[64 + lane * 2] = __floats2half2_rn(l1.x, l1.y);
        outr[65 + lane * 2] = __floats2half2_rn(l1.z, l1.w);
    } else {
        float4 e0, e1;
        e0.x = fexp(l0.x); e0.y = fexp(l0.y); e0.z = fexp(l0.z); e0.w = fexp(l0.w);
        e1.x = fexp(l1.x); e1.y = fexp(l1.y); e1.z = fexp(l1.z); e1.w = fexp(l1.w);
        float se = e0.x + e0.y + e0.z + e0.w + e1.x + e1.y + e1.z + e1.w;
        #pragma unroll
        for (int o = 16; o > 0; o >>= 1) se += __shfl_xor_sync(0xffffffffu, se, o);
        __half2* qer = (__half2*)(qe + row * C_);
        qer[lane * 2]      = __floats2half2_rn(e0.x, e0.y);
        qer[lane * 2 + 1]  = __floats2half2_rn(e0.z, e0.w);
        qer[64 + lane * 2] = __floats2half2_rn(e1.x, e1.y);
        qer[65 + lane * 2] = __floats2half2_rn(e1.z, e1.w);
        if (lane == 0) qs[row] = se;
    }
}

// ---------------- zero + column sum (S) ----------------------------------------
__global__ void zero_kernel(float* __restrict__ p, int n) {
    int i = blockIdx.x * 256 + threadIdx.x;
    if (i < n) p[i] = 0.f;
}
__global__ void colsum_kernel(const __half* __restrict__ qe, float* __restrict__ S) {
    int b = blockIdx.y, ch = blockIdx.x, t = threadIdx.x;
    const __half* base = qe + ((size_t)b * N_ + (size_t)ch * CR_) * C_ + t;
    float s = 0.f;
    #pragma unroll 8
    for (int r = 0; r < CR_; r++) s += __half2float(base[(size_t)r * C_]);
    atomicAdd(&S[b * C_ + t], s);
}

// ---------------- context GEMM: fp16 mma + ldmatrix, k32 stages ----------------
#define CROW 136                       // halves per smem row (272B)
#define CAB32 (32 * CROW * 2)          // bytes per operand tile (k32) = 8704
#define CSTAGEB (2 * CAB32)            // 17408 B per stage
#define CSMEM (3 * CSTAGEB)            // 52224 B
__global__ __launch_bounds__(256) void ctx_gemm(
        const __half* __restrict__ qe, const __half* __restrict__ n1,
        float* __restrict__ ctxp) {
    extern __shared__ __align__(16) __half cbuf[];
    int bz = blockIdx.z;
    int b = bz / KS_, sk = bz % KS_;
    int m0 = blockIdx.y * 128, n0 = blockIdx.x * 128;
    const __half* A  = qe + (size_t)b * N_ * C_;
    const __half* Bx = n1 + (size_t)b * N_ * C_;

    int t = threadIdx.x;
    int warp = t >> 5, lane = t & 31;
    int g = lane >> 2, tg = lane & 3;
    int wm = (warp >> 2) * 64, wn = (warp & 3) * 32;
    int l8 = lane & 7, grp = lane >> 3, grpB = grp & 1;
    int ldrow = t >> 4, ldch = t & 15;   // loader: 16 rows x 16 chunks per pass
    int kbase = sk * CHK_;
    uint cbase = smem_u32(cbuf);

    uint aoff[4], boff[4];
    #pragma unroll
    for (int mt = 0; mt < 4; mt++)
        aoff[mt] = (uint)(((l8 + (grp >> 1) * 8) * CROW + wm + mt * 16 + (grp & 1) * 8) * 2);
    #pragma unroll
    for (int nt = 0; nt < 4; nt++)
        boff[nt] = (uint)(((l8 + grpB * 8) * CROW + wn + nt * 8) * 2) + CAB32;

    float4 acc[4][4];
    #pragma unroll
    for (int i = 0; i < 4; i++)
        #pragma unroll
        for (int j = 0; j < 4; j++) acc[i][j] = make_float4(0.f, 0.f, 0.f, 0.f);

    auto ISSUE = [&](int kt, int buf) {
        uint base = cbase + (uint)buf * CSTAGEB;
        #pragma unroll
        for (int h = 0; h < 2; h++) {   // two 16-row passes = 32 k rows
            int rg = kbase + kt * 32 + h * 16 + ldrow;
            uint so = (uint)(((h * 16 + ldrow) * CROW + ldch * 8) * 2);
            cp16(base + so, &A[(size_t)rg * C_ + m0 + ldch * 8]);
            cp16(base + CAB32 + so, &Bx[(size_t)rg * C_ + n0 + ldch * 8]);
        }
        CP_COMMIT();
    };

    const int NT = CHK_ / 32;   // 36
    ISSUE(0, 0);
    ISSUE(1, 1);
    for (int kt = 0; kt < NT; kt++) {
        if (kt < NT - 1) { CP_WAIT1(); } else { CP_WAIT0(); }
        __syncthreads();
        if (kt + 2 < NT) ISSUE(kt + 2, (kt + 2) % 3);
        uint sbase = cbase + (uint)(kt % 3) * CSTAGEB;
        #pragma unroll
        for (int ks = 0; ks < 2; ks++) {
            uint ko = (uint)(ks * 16 * CROW * 2);
            uint a[4][4], bf[4][2];
            #pragma unroll
            for (int mt = 0; mt < 4; mt++) ldsm4t(a[mt], sbase + ko + aoff[mt]);
            #pragma unroll
            for (int nt = 0; nt < 4; nt++) ldsm2t(bf[nt], sbase + ko + boff[nt]);
            #pragma unroll
            for (int mt = 0; mt < 4; mt++)
                #pragma unroll
                for (int nt = 0; nt < 4; nt++)
                    mma16(acc[mt][nt], a[mt], bf[nt]);
        }
    }

    float* dst = ctxp + ((size_t)sk * B_ + b) * C_ * C_;
    #pragma unroll
    for (int mt = 0; mt < 4; mt++) {
        int row = m0 + wm + mt * 16 + g;
        #pragma unroll
        for (int nt = 0; nt < 4; nt++) {
            int col = n0 + wn + nt * 8 + tg * 2;
            *(float2*)&dst[(size_t)row * C_ + col] = make_float2(acc[mt][nt].x, acc[mt][nt].y);
            *(float2*)&dst[(size_t)(row + 8) * C_ + col] = make_float2(acc[mt][nt].z, acc[mt][nt].w);
        }
    }
}

// ---------------- combined 4-way top-k masked softmax --------------------------
__global__ void topk_kernel(const float* __restrict__ ctxp, float* __restrict__ ctx,
                            const float* __restrict__ aw, const float* __restrict__ Sg) {
    __shared__ ull sk_[C_];
    __shared__ float shm[1];
    __shared__ float s4[4][8];
    int row = blockIdx.x;
    int b = row >> 8, d = row & 255;
    int t = threadIdx.x;
    float v = 0.f;
    #pragma unroll
    for (int sk = 0; sk < KS_; sk++)
        v += ctxp[(((size_t)sk * B_ + b) * C_ + d) * C_ + t];
    v /= Sg[row];

    uint bits = __float_as_uint(v);
    uint su = bits ^ ((uint)((int)bits >> 31) | 0x80000000u);
    ull key = ((ull)su << 32) | (uint)(C_ - 1 - t);
    sk_[t] = key;
    __syncthreads();

    int rank = 0;
    #pragma unroll 8
    for (int f = 0; f < C_; f++) rank += (sk_[f] > key);

    if (rank == 0) shm[0] = v;
    __syncthreads();
    float m = shm[0];
    float e = fexp(v - m);

    float z1 = (rank < 128) ? e : 0.f;
    float z2 = (rank < 170) ? e : 0.f;
    float z3 = (rank < 192) ? e : 0.f;
    float z4 = (rank < 204) ? e : 0.f;
    #pragma unroll
    for (int o = 16; o > 0; o >>= 1) {
        z1 += __shfl_xor_sync(0xffffffffu, z1, o);
        z2 += __shfl_xor_sync(0xffffffffu, z2, o);
        z3 += __shfl_xor_sync(0xffffffffu, z3, o);
        z4 += __shfl_xor_sync(0xffffffffu, z4, o);
    }
    int warp = t >> 5;
    if ((t & 31) == 0) {
        s4[0][warp] = z1; s4[1][warp] = z2; s4[2][warp] = z3; s4[3][warp] = z4;
    }
    __syncthreads();
    float Z1 = 0.f, Z2 = 0.f, Z3 = 0.f, Z4 = 0.f;
    #pragma unroll
    for (int wq = 0; wq < 8; wq++) {
        Z1 += s4[0][wq]; Z2 += s4[1][wq]; Z3 += s4[2][wq]; Z4 += s4[3][wq];
    }
    float coeff = 0.f;
    if (rank < 128) coeff += aw[0] / Z1;
    if (rank < 170) coeff += aw[1] / Z2;
    if (rank < 192) coeff += aw[2] / Z3;
    if (rank < 204) coeff += aw[3] / Z4;
    ctx[(size_t)row * C_ + t] = e * coeff;
}

// ---------------- small GEMM (F1): WA = fp16(reproj_w @ A) ---------------------
__global__ void gemm64(const float* __restrict__ A, const float* __restrict__ B,
                       __half* __restrict__ C,
                       int K, size_t sA, size_t sB, size_t sC,
                       int lda, int ldb, int ldc) {
    int bz = blockIdx.z;
    const float* Ab = A + (size_t)bz * sA;
    const float* Bb = B + (size_t)bz * sB;
    __half* Cb = C + (size_t)bz * sC;
    int m0 = blockIdx.y * 64, n0 = blockIdx.x * 64;
    __shared__ float sa[16][65];
    __shared__ float sb[16][64];
    int t = threadIdx.x;
    int tx = t % 16, ty = t / 16;
    int r_ld = t / 16, kk_lda = t % 16;
    int c_ld = t % 64, kk_ldb = t / 64;
    float acc[4][4] = {};
    for (int k0 = 0; k0 < K; k0 += 16) {
        __syncthreads();
        #pragma unroll
        for (int it = 0; it < 4; it++) {
            sa[kk_lda][r_ld + 16 * it] = Ab[(size_t)(m0 + r_ld + 16 * it) * lda + k0 + kk_lda];
            sb[kk_ldb + 4 * it][c_ld] = Bb[(size_t)(k0 + kk_ldb + 4 * it) * ldb + n0 + c_ld];
        }
        __syncthreads();
        #pragma unroll
        for (int kk = 0; kk < 16; kk++) {
            float av[4], bv[4];
            #pragma unroll
            for (int i = 0; i < 4; i++) av[i] = sa[kk][ty + 16 * i];
            #pragma unroll
            for (int j = 0; j < 4; j++) bv[j] = sb[kk][tx + 16 * j];
            #pragma unroll
            for (int i = 0; i < 4; i++)
                #pragma unroll
                for (int j = 0; j < 4; j++) acc[i][j] = fmaf(av[i], bv[j], acc[i][j]);
        }
    }
    #pragma unroll
    for (int i = 0; i < 4; i++)
        #pragma unroll
        for (int j = 0; j < 4; j++)
            Cb[(size_t)(m0 + ty + 16 * i) * ldc + n0 + tx + 16 * j] = __float2half_rn(acc[i][j]);
}

// ---------------- final: k32 stages, fp16 mma -----------------------------------
#define FROW 40                          // halves per smem row (80B, bank-clean)
#define FSTAGEB ((64 + 512) * FROW * 2)  // 46080 B per k32 stage
#define FSMEM   (3 * FSTAGEB)            // 138240 B
__global__ __launch_bounds__(512) void final_kernel(
        const __half* __restrict__ qe, const float* __restrict__ qsg,
        const __half* __restrict__ WA,
        const float* __restrict__ rbias, const float* __restrict__ w2g,
        const float* __restrict__ b2g, float* __restrict__ out) {
    extern __shared__ __align__(16) uint pool[];

    int bb = blockIdx.y;
    int n0 = blockIdx.x * 64;
    const __half* qb  = qe + (size_t)bb * N_ * C_ + (size_t)n0 * C_;
    const __half* WAb = WA + (size_t)bb * O_ * C_;

    int t = threadIdx.x, warp = t >> 5, lane = t & 31, g = lane >> 2, tg = lane & 3;
    int o0 = warp * 32;
    int l8 = lane & 7, grp = lane >> 3, grpB = grp & 1;
    uint abase = smem_u32(pool);

    uint aoff[4], boff[4];
    #pragma unroll
    for (int mt = 0; mt < 4; mt++)
        aoff[mt] = (uint)(((mt * 16 + l8 + (grp & 1) * 8) * FROW + (grp >> 1) * 8) * 2);
    #pragma unroll
    for (int nt = 0; nt < 4; nt++)
        boff[nt] = (uint)(((64 + o0 + nt * 8 + l8) * FROW + grpB * 8) * 2);

    float4 acc[4][4];
    #pragma unroll
    for (int i = 0; i < 4; i++)
        #pragma unroll
        for (int j = 0; j < 4; j++) acc[i][j] = make_float4(0.f, 0.f, 0.f, 0.f);

    auto ISSUE = [&](int kt, int buf) {
        int k0 = kt * 32;
        uint base = abase + (uint)buf * FSTAGEB;
        #pragma unroll
        for (int i = 0; i < 5; i++) {
            int c = t + 512 * i;
            if (i < 4 || t < 256) {        // 2304 chunks total
                int row = c >> 2, quad = c & 3;
                const __half* src = (row < 64)
                    ? &qb[(size_t)row * C_ + k0 + quad * 8]
                    : &WAb[(size_t)(row - 64) * C_ + k0 + quad * 8];
                cp16(base + (uint)((row * FROW + quad * 8) * 2), src);
            }
        }
        CP_COMMIT();
    };

    const int NT = C_ / 32;   // 8
    ISSUE(0, 0);
    ISSUE(1, 1);
    for (int kt = 0; kt < NT; kt++) {
        if (kt < NT - 1) { CP_WAIT1(); } else { CP_WAIT0(); }
        __syncthreads();
        if (kt + 2 < NT) ISSUE(kt + 2, (kt + 2) % 3);
        uint sbase = abase + (uint)(kt % 3) * FSTAGEB;
        #pragma unroll
        for (int ks = 0; ks < 2; ks++) {
            uint ko = (uint)(ks * 16 * 2);   // 16 halves along the row
            uint a[4][4], bf[4][2];
            #pragma unroll
            for (int mt = 0; mt < 4; mt++) ldsm4(a[mt], sbase + ko + aoff[mt]);
            #pragma unroll
            for (int nt = 0; nt < 4; nt++) ldsm2(bf[nt], sbase + ko + boff[nt]);
            #pragma unroll
            for (int mt = 0; mt < 4; mt++)
                #pragma unroll
                for (int nt = 0; nt < 4; nt++)
                    mma16(acc[mt][nt], a[mt], bf[nt]);
        }
    }
    __syncthreads();

    // ---- epilogue (pool reused) ----
    float* redS = (float*)pool;
    float* redQ = (float*)(pool + 1024);
    float* muS  = (float*)(pool + 2048);
    float* rsS  = (float*)(pool + 2112);
    float* sout = (float*)(pool + 2176);

    const float* qsb = qsg + (size_t)bb * N_ + n0;
    float i1[4], i2[4];
    #pragma unroll
    for (int mt = 0; mt < 4; mt++) {
        i1[mt] = 1.f / qsb[mt * 16 + g];
        i2[mt] = 1.f / qsb[mt * 16 + g + 8];
    }
    #pragma unroll
    for (int nt = 0; nt < 4; nt++) {
        int o = o0 + nt * 8 + tg * 2;
        float2 rb = *(const float2*)&rbias[o];
        #pragma unroll
        for (int mt = 0; mt < 4; mt++) {
            acc[mt][nt].x = acc[mt][nt].x * i1[mt] + rb.x;
            acc[mt][nt].y = acc[mt][nt].y * i1[mt] + rb.y;
            acc[mt][nt].z = acc[mt][nt].z * i2[mt] + rb.x;
            acc[mt][nt].w = acc[mt][nt].w * i2[mt] + rb.y;
        }
    }

    #pragma unroll
    for (int mt = 0; mt < 4; mt++) {
        float sA = 0.f, qA = 0.f, sB = 0.f, qB = 0.f;
        #pragma unroll
        for (int nt = 0; nt < 4; nt++) {
            float4 a = acc[mt][nt];
            sA += a.x + a.y; qA += a.x * a.x + a.y * a.y;
            sB += a.z + a.w; qB += a.z * a.z + a.w * a.w;
        }
        #pragma unroll
        for (int o = 1; o <= 2; o <<= 1) {
            sA += __shfl_xor_sync(0xffffffffu, sA, o);
            qA += __shfl_xor_sync(0xffffffffu, qA, o);
            sB += __shfl_xor_sync(0xffffffffu, sB, o);
            qB += __shfl_xor_sync(0xffffffffu, qB, o);
        }
        if (tg == 0) {
            redS[warp * 64 + mt * 16 + g] = sA;
            redQ[warp * 64 + mt * 16 + g] = qA;
            redS[warp * 64 + mt * 16 + g + 8] = sB;
            redQ[warp * 64 + mt * 16 + g + 8] = qB;
        }
    }
    __syncthreads();
    if (t < 64) {
        float s = 0.f, qq = 0.f;
        #pragma unroll
        for (int w = 0; w < 16; w++) { s += redS[w * 64 + t]; qq += redQ[w * 64 + t]; }
        float mu = s * (1.f / O_);
        float var = qq * (1.f / O_) - mu * mu;
        muS[t] = mu;
        rsS[t] = rsqrtf(var + LN_EPS);
    }
    __syncthreads();
    float mu1[4], rs1[4], mu2[4], rs2[4];
    #pragma unroll
    for (int mt = 0; mt < 4; mt++) {
        mu1[mt] = muS[mt * 16 + g];     rs1[mt] = rsS[mt * 16 + g];
        mu2[mt] = muS[mt * 16 + g + 8]; rs2[mt] = rsS[mt * 16 + g + 8];
    }
    __syncthreads();

    #pragma unroll
    for (int p = 0; p < 4; p++) {
        if ((warp >> 2) == p) {
            int obase = (warp & 3) * 32;
            #pragma unroll
            for (int nt = 0; nt < 4; nt++) {
                int ol = obase + nt * 8 + tg * 2;
                int o = p * 128 + ol;
                float2 wv = *(const float2*)&w2g[o];
                float2 bv = *(const float2*)&b2g[o];
                #pragma unroll
                for (int mt = 0; mt < 4; mt++) {
                    int r1 = mt * 16 + g, r2 = r1 + 8;
                    float4 a = acc[mt][nt];
                    sout[ol * 68 + r1]       = (a.x - mu1[mt]) * rs1[mt] * wv.x + bv.x;
                    sout[(ol + 1) * 68 + r1] = (a.y - mu1[mt]) * rs1[mt] * wv.y + bv.y;
                    sout[ol * 68 + r2]       = (a.z - mu2[mt]) * rs2[mt] * wv.x + bv.x;
                    sout[(ol + 1) * 68 + r2] = (a.w - mu2[mt]) * rs2[mt] * wv.y + bv.y;
                }
            }
        }
        __syncthreads();
        #pragma unroll
        for (int i = 0; i < 4; i++) {
            int idx = t + 512 * i;
            int ol = idx >> 4, nn = (idx & 15) * 4;
            float4 v = *(float4*)&sout[ol * 68 + nn];
            *(float4*)&out[((size_t)bb * O_ + p * 128 + ol) * N_ + n0 + nn] = v;
        }
        __syncthreads();
    }
}

// ---------------- launch --------------------------------------------------------
extern "C" void kernel_launch(void* const* d_in, const int* in_sizes, int n_in,
                              void* d_out, int out_size) {
    const float* x1       = (const float*)d_in[0];
    const float* x2       = (const float*)d_in[1];
    const float* norm1_w  = (const float*)d_in[2];
    const float* norm1_b  = (const float*)d_in[3];
    const float* reproj_w = (const float*)d_in[4];
    const float* reproj_b = (const float*)d_in[5];
    const float* norm2_w  = (const float*)d_in[6];
    const float* norm2_b  = (const float*)d_in[7];
    const float* attn_w   = (const float*)d_in[8];
    float* out = (float*)d_out;

    __half *qe, *n1, *WA;
    float *qs, *S, *ctxp, *ctx;
    cudaGetSymbolAddress((void**)&qe,   g_qe);
    cudaGetSymbolAddress((void**)&qs,   g_qs);
    cudaGetSymbolAddress((void**)&n1,   g_n1);
    cudaGetSymbolAddress((void**)&S,    g_S);
    cudaGetSymbolAddress((void**)&ctxp, g_ctxp);
    cudaGetSymbolAddress((void**)&ctx,  g_ctx);
    cudaGetSymbolAddress((void**)&WA,   g_WA);

    cudaFuncSetAttribute(ctx_gemm,
                         cudaFuncAttributeMaxDynamicSharedMemorySize, CSMEM);
    cudaFuncSetAttribute(final_kernel,
                         cudaFuncAttributeMaxDynamicSharedMemorySize, FSMEM);

    prod_kernel<<<dim3(B_ * N_ / 8, 2), 256>>>(x1, x2, norm1_w, norm1_b, n1, qe, qs);
    zero_kernel<<<(B_ * C_ + 255) / 256, 256>>>(S, B_ * C_);
    colsum_kernel<<<dim3(NCH_, B_), 256>>>(qe, S);

    ctx_gemm<<<dim3(2, 2, B_ * KS_), 256, CSMEM>>>(qe, n1, ctxp);

    topk_kernel<<<B_ * C_, 256>>>(ctxp, ctx, attn_w, S);

    gemm64<<<dim3(C_ / 64, O_ / 64, B_), 256>>>(
        reproj_w, ctx, WA, C_,
        (size_t)0, (size_t)C_ * C_, (size_t)O_ * C_,
        C_, C_, C_);

    final_kernel<<<dim3(N_ / 64, B_), 512, FSMEM>>>(
        qe, qs, WA, reproj_b, norm2_w, norm2_b, out);
}